// round 5
// baseline (speedup 1.0000x reference)
#include <cuda_runtime.h>
#include <math.h>

#define T_   2048
#define B_   512
#define IN_  32
#define H_   256
#define ROWS_ 4
#define NBLK_ (B_ / ROWS_)
#define DT_C  0.1f
#define EPS_C 1e-5f

__device__ __forceinline__ float sigf(float z) { return 1.0f / (1.0f + expf(-z)); }

__global__ void __launch_bounds__(H_, 1)
liquid_kernel(const float* __restrict__ x,
              const float* __restrict__ Win0,  const float* __restrict__ bin0,
              const float* __restrict__ Wrec0, const float* __restrict__ brec0,
              const float* __restrict__ Wattn0,const float* __restrict__ battn0,
              const float* __restrict__ Wev0,  const float* __restrict__ bev0,
              const float* __restrict__ tau0,  const float* __restrict__ gamma0,
              const float* __restrict__ beta0,
              const float* __restrict__ Win1,  const float* __restrict__ bin1,
              const float* __restrict__ Wrec1, const float* __restrict__ brec1,
              const float* __restrict__ Wattn1,const float* __restrict__ battn1,
              const float* __restrict__ Wev1,  const float* __restrict__ bev1,
              const float* __restrict__ tau1,  const float* __restrict__ gamma1,
              const float* __restrict__ beta1,
              const float* __restrict__ Wskip, const float* __restrict__ bskip,
              const float* __restrict__ Wout,  const float* __restrict__ bout,
              float* __restrict__ out)
{
    // States packed as float4 over ROWS_=4 batch rows: buf[k] = {row0,row1,row2,row3}
    __shared__ float4 h0s[H_], h1s[H_], p1s[H_], gbuf[H_], h0ns[H_], tbuf[H_];
    __shared__ float4 xts[IN_], p0s[IN_];
    __shared__ float4 redbuf[8];
    __shared__ float  wev0s[2 * IN_];
    __shared__ float  ew0sh[ROWS_], ew1sh[ROWS_], mush[ROWS_], rsh[ROWS_];

    const int j    = threadIdx.x;      // feature index 0..255
    const int lane = j & 31;
    const int wid  = j >> 5;
    const int b0   = blockIdx.x * ROWS_;

    // ---- per-feature constants (registers, loaded once) ----
    const float c_bin0 = bin0[j],  c_ba0 = battn0[j], c_br0 = brec0[j];
    const float c_bin1 = bin1[j],  c_ba1 = battn1[j], c_br1 = brec1[j];
    const float c_g0   = gamma0[j], c_be0 = beta0[j];
    const float c_g1   = gamma1[j], c_be1 = beta1[j];
    const float c_bsk  = bskip[j];
    const float rt0 = DT_C / fminf(fmaxf(tau0[j], 0.1f), 10.0f);
    const float rt1 = DT_C / fminf(fmaxf(tau1[j], 0.1f), 10.0f);
    const float wv1a = Wev1[j], wv1b = Wev1[H_ + j];
    const float c_wout = Wout[j];
    const float c_bev0 = bev0[0], c_bev1 = bev1[0], c_bout = bout[0];

    if (j < 2 * IN_) wev0s[j] = Wev0[j];
    const float4 z4 = make_float4(0.f, 0.f, 0.f, 0.f);
    h0s[j] = z4; h1s[j] = z4; p1s[j] = z4;
    if (j < IN_) p0s[j] = z4;
    __syncthreads();

    float* ew0o = out + B_;
    float* ew1o = out + B_ + (size_t)B_ * T_;

    for (int t = 0; t < T_; ++t) {
        // ---------- load x_t, rows packed ----------
        if (j < IN_) {
            float4 v;
            v.x = x[((size_t)(b0 + 0) * T_ + t) * IN_ + j];
            v.y = x[((size_t)(b0 + 1) * T_ + t) * IN_ + j];
            v.z = x[((size_t)(b0 + 2) * T_ + t) * IN_ + j];
            v.w = x[((size_t)(b0 + 3) * T_ + t) * IN_ + j];
            xts[j] = v;
        }
        __syncthreads();                                            // (a)

        // ---------- ew0 : sigmoid([xt,p0] @ Wev0 + b) * mask, warps 0..3 ----------
        if (wid < ROWS_) {
            const float* xf = (const float*)xts;
            const float* pf = (const float*)p0s;
            float s = xf[lane * 4 + wid] * wev0s[lane]
                    + pf[lane * 4 + wid] * wev0s[IN_ + lane];
            #pragma unroll
            for (int o = 16; o > 0; o >>= 1) s += __shfl_xor_sync(0xffffffffu, s, o);
            if (lane == 0) {
                float e = (t > 0) ? sigf(s + c_bev0) : 0.0f;
                ew0sh[wid] = e;
                ew0o[(size_t)(b0 + wid) * T_ + t] = e;
            }
        }

        // ---------- inp0 = tanh(xt @ Win0 + b) ----------
        float4 i0 = make_float4(c_bin0, c_bin0, c_bin0, c_bin0);
        #pragma unroll
        for (int i = 0; i < IN_; ++i) {
            float w = __ldg(&Win0[i * H_ + j]);
            float4 xv = xts[i];
            i0.x += w * xv.x; i0.y += w * xv.y; i0.z += w * xv.z; i0.w += w * xv.w;
        }

        // ---------- attn0 = sigmoid(h0 @ Wattn0 + b) ----------
        float4 a0 = make_float4(c_ba0, c_ba0, c_ba0, c_ba0);
        #pragma unroll 16
        for (int k = 0; k < H_; ++k) {
            float w = __ldg(&Wattn0[k * H_ + j]);
            float4 hv = h0s[k];
            a0.x += w * hv.x; a0.y += w * hv.y; a0.z += w * hv.z; a0.w += w * hv.w;
        }
        a0.x = sigf(a0.x); a0.y = sigf(a0.y); a0.z = sigf(a0.z); a0.w = sigf(a0.w);
        const float4 h0j = h0s[j];
        gbuf[j] = make_float4(h0j.x * a0.x, h0j.y * a0.y, h0j.z * a0.z, h0j.w * a0.w);
        __syncthreads();                                            // (b)

        // ---------- rec0 = tanh((h0*attn0) @ Wrec0 + b); pre-LN update ----------
        float4 r0 = make_float4(c_br0, c_br0, c_br0, c_br0);
        #pragma unroll 16
        for (int k = 0; k < H_; ++k) {
            float w = __ldg(&Wrec0[k * H_ + j]);
            float4 gv = gbuf[k];
            r0.x += w * gv.x; r0.y += w * gv.y; r0.z += w * gv.z; r0.w += w * gv.w;
        }
        float4 pre;
        {
            const float e0 = 1.f + ew0sh[0], e1 = 1.f + ew0sh[1];
            const float e2 = 1.f + ew0sh[2], e3 = 1.f + ew0sh[3];
            pre.x = h0j.x + rt0 * (-h0j.x + tanhf(i0.x) + tanhf(r0.x)) * e0;
            pre.y = h0j.y + rt0 * (-h0j.y + tanhf(i0.y) + tanhf(r0.y)) * e1;
            pre.z = h0j.z + rt0 * (-h0j.z + tanhf(i0.z) + tanhf(r0.z)) * e2;
            pre.w = h0j.w + rt0 * (-h0j.w + tanhf(i0.w) + tanhf(r0.w)) * e3;
        }
        tbuf[j] = pre;
        __syncthreads();                                            // (c)

        // ---------- LN0 statistics (warp per row) ----------
        if (wid < ROWS_) {
            const float* tf = (const float*)tbuf;
            float s = 0.f, ss = 0.f;
            #pragma unroll
            for (int m = 0; m < H_ / 32; ++m) {
                float v = tf[(lane + 32 * m) * 4 + wid];
                s += v; ss += v * v;
            }
            #pragma unroll
            for (int o = 16; o > 0; o >>= 1) {
                s  += __shfl_xor_sync(0xffffffffu, s, o);
                ss += __shfl_xor_sync(0xffffffffu, ss, o);
            }
            if (lane == 0) {
                float mu = s * (1.0f / H_);
                float var = ss * (1.0f / H_) - mu * mu;
                mush[wid] = mu;
                rsh[wid] = rsqrtf(var + EPS_C);
            }
        }
        __syncthreads();                                            // (d)

        // ---------- h0n = LN(pre); publish; ew1 partial reductions ----------
        float4 hn;
        hn.x = (pre.x - mush[0]) * rsh[0] * c_g0 + c_be0;
        hn.y = (pre.y - mush[1]) * rsh[1] * c_g0 + c_be0;
        hn.z = (pre.z - mush[2]) * rsh[2] * c_g0 + c_be0;
        hn.w = (pre.w - mush[3]) * rsh[3] * c_g0 + c_be0;
        h0ns[j] = hn;
        {
            const float4 pv = p1s[j];
            float4 part;
            part.x = hn.x * wv1a + pv.x * wv1b;
            part.y = hn.y * wv1a + pv.y * wv1b;
            part.z = hn.z * wv1a + pv.z * wv1b;
            part.w = hn.w * wv1a + pv.w * wv1b;
            #pragma unroll
            for (int o = 16; o > 0; o >>= 1) {
                part.x += __shfl_xor_sync(0xffffffffu, part.x, o);
                part.y += __shfl_xor_sync(0xffffffffu, part.y, o);
                part.z += __shfl_xor_sync(0xffffffffu, part.z, o);
                part.w += __shfl_xor_sync(0xffffffffu, part.w, o);
            }
            if (lane == 0) redbuf[wid] = part;
        }
        __syncthreads();                                            // (e)

        if (j < ROWS_) {
            const float* rf = (const float*)redbuf;
            float s = c_bev1;
            #pragma unroll
            for (int w = 0; w < 8; ++w) s += rf[w * 4 + j];
            float e = (t > 0) ? sigf(s) : 0.0f;
            ew1sh[j] = e;
            ew1o[(size_t)(b0 + j) * T_ + t] = e;
        }

        // ---------- fused: attn1 (h1), inp1 (h0n), skip (h0n) ----------
        float4 a1 = make_float4(c_ba1, c_ba1, c_ba1, c_ba1);
        float4 i1 = make_float4(c_bin1, c_bin1, c_bin1, c_bin1);
        float4 sk = make_float4(c_bsk, c_bsk, c_bsk, c_bsk);
        #pragma unroll 8
        for (int k = 0; k < H_; ++k) {
            float wa = __ldg(&Wattn1[k * H_ + j]);
            float wi = __ldg(&Win1[k * H_ + j]);
            float ws = __ldg(&Wskip[k * H_ + j]);
            float4 h1v = h1s[k];
            float4 hnv = h0ns[k];
            a1.x += wa * h1v.x; a1.y += wa * h1v.y; a1.z += wa * h1v.z; a1.w += wa * h1v.w;
            i1.x += wi * hnv.x; i1.y += wi * hnv.y; i1.z += wi * hnv.z; i1.w += wi * hnv.w;
            sk.x += ws * hnv.x; sk.y += ws * hnv.y; sk.z += ws * hnv.z; sk.w += ws * hnv.w;
        }
        a1.x = sigf(a1.x); a1.y = sigf(a1.y); a1.z = sigf(a1.z); a1.w = sigf(a1.w);
        const float4 h1j = h1s[j];
        gbuf[j] = make_float4(h1j.x * a1.x, h1j.y * a1.y, h1j.z * a1.z, h1j.w * a1.w);
        __syncthreads();                                            // (f)

        // ---------- rec1; pre-LN layer-1 update ----------
        float4 r1 = make_float4(c_br1, c_br1, c_br1, c_br1);
        #pragma unroll 16
        for (int k = 0; k < H_; ++k) {
            float w = __ldg(&Wrec1[k * H_ + j]);
            float4 gv = gbuf[k];
            r1.x += w * gv.x; r1.y += w * gv.y; r1.z += w * gv.z; r1.w += w * gv.w;
        }
        {
            const float e0 = 1.f + ew1sh[0], e1 = 1.f + ew1sh[1];
            const float e2 = 1.f + ew1sh[2], e3 = 1.f + ew1sh[3];
            pre.x = h1j.x + rt1 * (-h1j.x + tanhf(i1.x) + tanhf(r1.x)) * e0;
            pre.y = h1j.y + rt1 * (-h1j.y + tanhf(i1.y) + tanhf(r1.y)) * e1;
            pre.z = h1j.z + rt1 * (-h1j.z + tanhf(i1.z) + tanhf(r1.z)) * e2;
            pre.w = h1j.w + rt1 * (-h1j.w + tanhf(i1.w) + tanhf(r1.w)) * e3;
        }
        tbuf[j] = pre;
        __syncthreads();                                            // (g)

        // ---------- LN1 statistics ----------
        if (wid < ROWS_) {
            const float* tf = (const float*)tbuf;
            float s = 0.f, ss = 0.f;
            #pragma unroll
            for (int m = 0; m < H_ / 32; ++m) {
                float v = tf[(lane + 32 * m) * 4 + wid];
                s += v; ss += v * v;
            }
            #pragma unroll
            for (int o = 16; o > 0; o >>= 1) {
                s  += __shfl_xor_sync(0xffffffffu, s, o);
                ss += __shfl_xor_sync(0xffffffffu, ss, o);
            }
            if (lane == 0) {
                float mu = s * (1.0f / H_);
                float var = ss * (1.0f / H_) - mu * mu;
                mush[wid] = mu;
                rsh[wid] = rsqrtf(var + EPS_C);
            }
        }
        __syncthreads();                                            // (h)

        // ---------- finalize states ----------
        float4 h1n;
        h1n.x = (pre.x - mush[0]) * rsh[0] * c_g1 + c_be1 + sk.x;
        h1n.y = (pre.y - mush[1]) * rsh[1] * c_g1 + c_be1 + sk.y;
        h1n.z = (pre.z - mush[2]) * rsh[2] * c_g1 + c_be1 + sk.z;
        h1n.w = (pre.w - mush[3]) * rsh[3] * c_g1 + c_be1 + sk.w;
        h1s[j] = h1n;
        h0s[j] = hn;
        p1s[j] = hn;
        if (j < IN_) p0s[j] = xts[j];
        __syncthreads();                                            // (i)
    }

    // ---------- output head: out[b] = h1 @ Wout + bout ----------
    {
        const float4 h1j = h1s[j];
        float4 part = make_float4(h1j.x * c_wout, h1j.y * c_wout,
                                  h1j.z * c_wout, h1j.w * c_wout);
        #pragma unroll
        for (int o = 16; o > 0; o >>= 1) {
            part.x += __shfl_xor_sync(0xffffffffu, part.x, o);
            part.y += __shfl_xor_sync(0xffffffffu, part.y, o);
            part.z += __shfl_xor_sync(0xffffffffu, part.z, o);
            part.w += __shfl_xor_sync(0xffffffffu, part.w, o);
        }
        if (lane == 0) redbuf[wid] = part;
        __syncthreads();
        if (j < ROWS_) {
            const float* rf = (const float*)redbuf;
            float s = c_bout;
            #pragma unroll
            for (int w = 0; w < 8; ++w) s += rf[w * 4 + j];
            out[b0 + j] = s;
        }
    }
}

extern "C" void kernel_launch(void* const* d_in, const int* in_sizes, int n_in,
                              void* d_out, int out_size)
{
    (void)in_sizes; (void)n_in; (void)out_size;
    const float* x      = (const float*)d_in[0];
    const float* Win0   = (const float*)d_in[1];
    const float* bin0   = (const float*)d_in[2];
    const float* Wrec0  = (const float*)d_in[3];
    const float* brec0  = (const float*)d_in[4];
    const float* Wattn0 = (const float*)d_in[5];
    const float* battn0 = (const float*)d_in[6];
    const float* Wev0   = (const float*)d_in[7];
    const float* bev0   = (const float*)d_in[8];
    const float* tau0   = (const float*)d_in[9];
    const float* gamma0 = (const float*)d_in[10];
    const float* beta0  = (const float*)d_in[11];
    const float* Win1   = (const float*)d_in[12];
    const float* bin1   = (const float*)d_in[13];
    const float* Wrec1  = (const float*)d_in[14];
    const float* brec1  = (const float*)d_in[15];
    const float* Wattn1 = (const float*)d_in[16];
    const float* battn1 = (const float*)d_in[17];
    const float* Wev1   = (const float*)d_in[18];
    const float* bev1   = (const float*)d_in[19];
    const float* tau1   = (const float*)d_in[20];
    const float* gamma1 = (const float*)d_in[21];
    const float* beta1  = (const float*)d_in[22];
    const float* Wskip  = (const float*)d_in[23];
    const float* bskip  = (const float*)d_in[24];
    const float* Wout   = (const float*)d_in[25];
    const float* bout   = (const float*)d_in[26];

    liquid_kernel<<<NBLK_, H_>>>(x,
        Win0, bin0, Wrec0, brec0, Wattn0, battn0, Wev0, bev0, tau0, gamma0, beta0,
        Win1, bin1, Wrec1, brec1, Wattn1, battn1, Wev1, bev1, tau1, gamma1, beta1,
        Wskip, bskip, Wout, bout, (float*)d_out);
}

// round 8
// speedup vs baseline: 2.0078x; 2.0078x over previous
#include <cuda_runtime.h>
#include <math.h>

#define T_   2048
#define B_   512
#define IN_  32
#define H_   256
#define ROWS_ 4
#define NBLK_ (B_ / ROWS_)
#define THREADS_ 512
#define DT_C  0.1f
#define EPS_C 1e-5f

__device__ __forceinline__ float sigf(float z) { return 1.0f / (1.0f + expf(-z)); }

// ---- packed f32x2 helpers (full IEEE fp32, 2 FMAs per instruction) ----
__device__ __forceinline__ unsigned long long pack_dup(float w) {
    unsigned long long r;
    unsigned int u = __float_as_uint(w);
    asm("mov.b64 %0, {%1, %1};" : "=l"(r) : "r"(u));
    return r;
}
__device__ __forceinline__ unsigned long long pack2(float a, float b) {
    unsigned long long r;
    asm("mov.b64 %0, {%1, %2};" : "=l"(r) : "r"(__float_as_uint(a)), "r"(__float_as_uint(b)));
    return r;
}
__device__ __forceinline__ void unpack2(unsigned long long v, float& a, float& b) {
    unsigned int lo, hi;
    asm("mov.b64 {%0, %1}, %2;" : "=r"(lo), "=r"(hi) : "l"(v));
    a = __uint_as_float(lo); b = __uint_as_float(hi);
}
__device__ __forceinline__ void fma2(unsigned long long& acc,
                                     unsigned long long a, unsigned long long b) {
    asm("fma.rn.f32x2 %0, %1, %2, %0;" : "+l"(acc) : "l"(a), "l"(b));
}

// Partial matvec over 128 k values (one K-half).
// w: weight column base already offset by (half*128)*H + j (stride H per k)
// st: state base + half*128 (float4 = rows 0..3)
__device__ __forceinline__ float4 mv_partial(const float* __restrict__ w,
                                             const float4* st)
{
    unsigned long long a01 = 0ull, a23 = 0ull;   // {0.f,0.f} packed
    #pragma unroll 16
    for (int k = 0; k < 128; ++k) {
        float wv = __ldg(&w[k * H_]);
        unsigned long long w2 = pack_dup(wv);
        float4 s = st[k];
        fma2(a01, w2, pack2(s.x, s.y));
        fma2(a23, w2, pack2(s.z, s.w));
    }
    float4 r;
    unpack2(a01, r.x, r.y);
    unpack2(a23, r.z, r.w);
    return r;
}

// Fused 3-matrix partial matvec (attn1 from h1; inp1 & skip from h0n).
__device__ __forceinline__ void mv_partial3(const float* __restrict__ wa,
                                            const float* __restrict__ wi,
                                            const float* __restrict__ ws,
                                            const float4* st_h1,
                                            const float4* st_h0n,
                                            float4& ra, float4& ri, float4& rs)
{
    unsigned long long aa01 = 0ull, aa23 = 0ull;
    unsigned long long ai01 = 0ull, ai23 = 0ull;
    unsigned long long as01 = 0ull, as23 = 0ull;
    #pragma unroll 8
    for (int k = 0; k < 128; ++k) {
        unsigned long long w2a = pack_dup(__ldg(&wa[k * H_]));
        unsigned long long w2i = pack_dup(__ldg(&wi[k * H_]));
        unsigned long long w2s = pack_dup(__ldg(&ws[k * H_]));
        float4 s1 = st_h1[k];
        float4 s0 = st_h0n[k];
        unsigned long long s1_01 = pack2(s1.x, s1.y), s1_23 = pack2(s1.z, s1.w);
        unsigned long long s0_01 = pack2(s0.x, s0.y), s0_23 = pack2(s0.z, s0.w);
        fma2(aa01, w2a, s1_01); fma2(aa23, w2a, s1_23);
        fma2(ai01, w2i, s0_01); fma2(ai23, w2i, s0_23);
        fma2(as01, w2s, s0_01); fma2(as23, w2s, s0_23);
    }
    unpack2(aa01, ra.x, ra.y); unpack2(aa23, ra.z, ra.w);
    unpack2(ai01, ri.x, ri.y); unpack2(ai23, ri.z, ri.w);
    unpack2(as01, rs.x, rs.y); unpack2(as23, rs.z, rs.w);
}

__global__ void __launch_bounds__(THREADS_, 1)
liquid_kernel(const float* __restrict__ x,
              const float* __restrict__ Win0,  const float* __restrict__ bin0,
              const float* __restrict__ Wrec0, const float* __restrict__ brec0,
              const float* __restrict__ Wattn0,const float* __restrict__ battn0,
              const float* __restrict__ Wev0,  const float* __restrict__ bev0,
              const float* __restrict__ tau0,  const float* __restrict__ gamma0,
              const float* __restrict__ beta0,
              const float* __restrict__ Win1,  const float* __restrict__ bin1,
              const float* __restrict__ Wrec1, const float* __restrict__ brec1,
              const float* __restrict__ Wattn1,const float* __restrict__ battn1,
              const float* __restrict__ Wev1,  const float* __restrict__ bev1,
              const float* __restrict__ tau1,  const float* __restrict__ gamma1,
              const float* __restrict__ beta1,
              const float* __restrict__ Wskip, const float* __restrict__ bskip,
              const float* __restrict__ Wout,  const float* __restrict__ bout,
              float* __restrict__ out)
{
    // States packed as float4 over ROWS_=4 batch rows
    __shared__ float4 h0s[H_], h1s[H_], p1s[H_], gbuf[H_], h0ns[H_], tbuf[H_];
    __shared__ float4 pb_a[H_], pb_b[H_], pb_c[H_];      // split-K partial buffers
    __shared__ float4 xts[IN_], p0s[IN_];
    __shared__ float4 redbuf[8];
    __shared__ float  wev0s[2 * IN_];
    __shared__ float  ew0sh[ROWS_], ew1sh[ROWS_], mush[ROWS_], rsh[ROWS_];

    const int tid  = threadIdx.x;
    const int j    = tid & 255;       // feature index
    const int half = tid >> 8;        // K-split half (0/1)
    const int lane = tid & 31;
    const int wid  = tid >> 5;        // 0..15
    const int b0   = blockIdx.x * ROWS_;
    const int so   = half * 128;      // state offset (float4 units) for this half

    // ---- per-feature constants ----
    const float c_bin0 = bin0[j],  c_ba0 = battn0[j], c_br0 = brec0[j];
    const float c_bin1 = bin1[j],  c_ba1 = battn1[j], c_br1 = brec1[j];
    const float c_g0   = gamma0[j], c_be0 = beta0[j];
    const float c_g1   = gamma1[j], c_be1 = beta1[j];
    const float c_bsk  = bskip[j];
    const float rt0 = DT_C / fminf(fmaxf(tau0[j], 0.1f), 10.0f);
    const float rt1 = DT_C / fminf(fmaxf(tau1[j], 0.1f), 10.0f);
    const float wv1a = Wev1[j], wv1b = Wev1[H_ + j];
    const float c_wout = Wout[j];
    const float c_bev0 = bev0[0], c_bev1 = bev1[0], c_bout = bout[0];

    // weight column base pointers, offset by K-half and feature column
    const int wofs = so * H_ + j;
    const float* Wa0 = Wattn0 + wofs;
    const float* Wr0 = Wrec0  + wofs;
    const float* Wa1 = Wattn1 + wofs;
    const float* Wi1 = Win1   + wofs;
    const float* Wsk = Wskip  + wofs;
    const float* Wr1 = Wrec1  + wofs;

    if (tid < 2 * IN_) wev0s[tid] = Wev0[tid];
    const float4 z4 = make_float4(0.f, 0.f, 0.f, 0.f);
    if (half == 0) { h0s[j] = z4; h1s[j] = z4; p1s[j] = z4; }
    if (tid < IN_) p0s[tid] = z4;
    __syncthreads();

    float* ew0o = out + B_;
    float* ew1o = out + B_ + (size_t)B_ * T_;

    for (int t = 0; t < T_; ++t) {
        // ---------- load x_t ----------
        if (tid < IN_) {
            float4 v;
            v.x = x[((size_t)(b0 + 0) * T_ + t) * IN_ + tid];
            v.y = x[((size_t)(b0 + 1) * T_ + t) * IN_ + tid];
            v.z = x[((size_t)(b0 + 2) * T_ + t) * IN_ + tid];
            v.w = x[((size_t)(b0 + 3) * T_ + t) * IN_ + tid];
            xts[tid] = v;
        }
        __syncthreads();                                            // (a)

        // ---------- ew0 (warps 0..3, fp32 exact) ----------
        if (wid < ROWS_) {
            const float* xf = (const float*)xts;
            const float* pf = (const float*)p0s;
            float s = xf[lane * 4 + wid] * wev0s[lane]
                    + pf[lane * 4 + wid] * wev0s[IN_ + lane];
            #pragma unroll
            for (int o = 16; o > 0; o >>= 1) s += __shfl_xor_sync(0xffffffffu, s, o);
            if (lane == 0) {
                float e = (t > 0) ? sigf(s + c_bev0) : 0.0f;
                ew0sh[wid] = e;
                ew0o[(size_t)(b0 + wid) * T_ + t] = e;
            }
        }

        // ---------- attn0 partial (both halves) + inp0 (half 0) ----------
        float4 a0p = mv_partial(Wa0, h0s + so);
        float4 i0  = make_float4(c_bin0, c_bin0, c_bin0, c_bin0);
        if (half == 0) {
            #pragma unroll
            for (int i = 0; i < IN_; ++i) {
                float w = Win0[i * H_ + j];
                float4 xv = xts[i];
                i0.x = fmaf(w, xv.x, i0.x); i0.y = fmaf(w, xv.y, i0.y);
                i0.z = fmaf(w, xv.z, i0.z); i0.w = fmaf(w, xv.w, i0.w);
            }
        } else {
            pb_a[j] = a0p;
        }
        __syncthreads();                                            // (b)

        // ---------- finalize attn0, publish gated state ----------
        float4 h0j;
        if (half == 0) {
            h0j = h0s[j];
            float4 p = pb_a[j];
            float4 a0;
            a0.x = sigf(a0p.x + p.x + c_ba0);
            a0.y = sigf(a0p.y + p.y + c_ba0);
            a0.z = sigf(a0p.z + p.z + c_ba0);
            a0.w = sigf(a0p.w + p.w + c_ba0);
            gbuf[j] = make_float4(h0j.x * a0.x, h0j.y * a0.y, h0j.z * a0.z, h0j.w * a0.w);
        }
        __syncthreads();                                            // (c)

        // ---------- rec0 partial ----------
        float4 r0p = mv_partial(Wr0, gbuf + so);
        if (half == 1) pb_a[j] = r0p;
        __syncthreads();                                            // (d)

        // ---------- pre-LN layer-0 update ----------
        float4 pre;
        if (half == 0) {
            float4 p = pb_a[j];
            float r0x = r0p.x + p.x + c_br0, r0y = r0p.y + p.y + c_br0;
            float r0z = r0p.z + p.z + c_br0, r0w = r0p.w + p.w + c_br0;
            const float e0 = 1.f + ew0sh[0], e1 = 1.f + ew0sh[1];
            const float e2 = 1.f + ew0sh[2], e3 = 1.f + ew0sh[3];
            pre.x = h0j.x + rt0 * (-h0j.x + tanhf(i0.x) + tanhf(r0x)) * e0;
            pre.y = h0j.y + rt0 * (-h0j.y + tanhf(i0.y) + tanhf(r0y)) * e1;
            pre.z = h0j.z + rt0 * (-h0j.z + tanhf(i0.z) + tanhf(r0z)) * e2;
            pre.w = h0j.w + rt0 * (-h0j.w + tanhf(i0.w) + tanhf(r0w)) * e3;
            tbuf[j] = pre;
        }
        __syncthreads();                                            // (e)

        // ---------- LN0 stats (warp per row) ----------
        if (wid < ROWS_) {
            const float* tf = (const float*)tbuf;
            float s = 0.f, ss = 0.f;
            #pragma unroll
            for (int m = 0; m < H_ / 32; ++m) {
                float v = tf[(lane + 32 * m) * 4 + wid];
                s += v; ss += v * v;
            }
            #pragma unroll
            for (int o = 16; o > 0; o >>= 1) {
                s  += __shfl_xor_sync(0xffffffffu, s, o);
                ss += __shfl_xor_sync(0xffffffffu, ss, o);
            }
            if (lane == 0) {
                float mu = s * (1.0f / H_);
                float var = ss * (1.0f / H_) - mu * mu;
                mush[wid] = mu;
                rsh[wid] = rsqrtf(var + EPS_C);
            }
        }
        __syncthreads();                                            // (f)

        // ---------- h0n = LN(pre); publish; ew1 warp partials ----------
        float4 hn;
        if (half == 0) {
            hn.x = (pre.x - mush[0]) * rsh[0] * c_g0 + c_be0;
            hn.y = (pre.y - mush[1]) * rsh[1] * c_g0 + c_be0;
            hn.z = (pre.z - mush[2]) * rsh[2] * c_g0 + c_be0;
            hn.w = (pre.w - mush[3]) * rsh[3] * c_g0 + c_be0;
            h0ns[j] = hn;
            h0s[j]  = hn;
            const float4 pv = p1s[j];
            float4 part;
            part.x = hn.x * wv1a + pv.x * wv1b;
            part.y = hn.y * wv1a + pv.y * wv1b;
            part.z = hn.z * wv1a + pv.z * wv1b;
            part.w = hn.w * wv1a + pv.w * wv1b;
            #pragma unroll
            for (int o = 16; o > 0; o >>= 1) {
                part.x += __shfl_xor_sync(0xffffffffu, part.x, o);
                part.y += __shfl_xor_sync(0xffffffffu, part.y, o);
                part.z += __shfl_xor_sync(0xffffffffu, part.z, o);
                part.w += __shfl_xor_sync(0xffffffffu, part.w, o);
            }
            if (lane == 0) redbuf[wid] = part;
        }
        __syncthreads();                                            // (g)

        if (tid < ROWS_) {
            const float* rf = (const float*)redbuf;
            float s = c_bev1;
            #pragma unroll
            for (int w = 0; w < 8; ++w) s += rf[w * 4 + tid];
            float e = (t > 0) ? sigf(s) : 0.0f;
            ew1sh[tid] = e;
            ew1o[(size_t)(b0 + tid) * T_ + t] = e;
        }

        // ---------- attn1 / inp1 / skip partials (both halves, fused) ----------
        float4 a1p, i1p, skp;
        mv_partial3(Wa1, Wi1, Wsk, h1s + so, h0ns + so, a1p, i1p, skp);
        if (half == 1) { pb_a[j] = a1p; pb_b[j] = i1p; pb_c[j] = skp; }
        __syncthreads();                                            // (h)

        float4 h1j, i1, sk;
        if (half == 0) {
            h1j = h1s[j];
            float4 pa = pb_a[j], pi = pb_b[j], ps = pb_c[j];
            float4 a1;
            a1.x = sigf(a1p.x + pa.x + c_ba1);
            a1.y = sigf(a1p.y + pa.y + c_ba1);
            a1.z = sigf(a1p.z + pa.z + c_ba1);
            a1.w = sigf(a1p.w + pa.w + c_ba1);
            i1 = make_float4(i1p.x + pi.x + c_bin1, i1p.y + pi.y + c_bin1,
                             i1p.z + pi.z + c_bin1, i1p.w + pi.w + c_bin1);
            sk = make_float4(skp.x + ps.x + c_bsk, skp.y + ps.y + c_bsk,
                             skp.z + ps.z + c_bsk, skp.w + ps.w + c_bsk);
            gbuf[j] = make_float4(h1j.x * a1.x, h1j.y * a1.y, h1j.z * a1.z, h1j.w * a1.w);
        }
        __syncthreads();                                            // (i)

        // ---------- rec1 partial ----------
        float4 r1p = mv_partial(Wr1, gbuf + so);
        if (half == 1) pb_a[j] = r1p;
        __syncthreads();                                            // (j)

        if (half == 0) {
            float4 p = pb_a[j];
            float r1x = r1p.x + p.x + c_br1, r1y = r1p.y + p.y + c_br1;
            float r1z = r1p.z + p.z + c_br1, r1w = r1p.w + p.w + c_br1;
            const float e0 = 1.f + ew1sh[0], e1 = 1.f + ew1sh[1];
            const float e2 = 1.f + ew1sh[2], e3 = 1.f + ew1sh[3];
            pre.x = h1j.x + rt1 * (-h1j.x + tanhf(i1.x) + tanhf(r1x)) * e0;
            pre.y = h1j.y + rt1 * (-h1j.y + tanhf(i1.y) + tanhf(r1y)) * e1;
            pre.z = h1j.z + rt1 * (-h1j.z + tanhf(i1.z) + tanhf(r1z)) * e2;
            pre.w = h1j.w + rt1 * (-h1j.w + tanhf(i1.w) + tanhf(r1w)) * e3;
            tbuf[j] = pre;
        }
        __syncthreads();                                            // (k)

        // ---------- LN1 stats ----------
        if (wid < ROWS_) {
            const float* tf = (const float*)tbuf;
            float s = 0.f, ss = 0.f;
            #pragma unroll
            for (int m = 0; m < H_ / 32; ++m) {
                float v = tf[(lane + 32 * m) * 4 + wid];
                s += v; ss += v * v;
            }
            #pragma unroll
            for (int o = 16; o > 0; o >>= 1) {
                s  += __shfl_xor_sync(0xffffffffu, s, o);
                ss += __shfl_xor_sync(0xffffffffu, ss, o);
            }
            if (lane == 0) {
                float mu = s * (1.0f / H_);
                float var = ss * (1.0f / H_) - mu * mu;
                mush[wid] = mu;
                rsh[wid] = rsqrtf(var + EPS_C);
            }
        }
        __syncthreads();                                            // (l)

        // ---------- finalize states ----------
        if (half == 0) {
            float4 h1n;
            h1n.x = (pre.x - mush[0]) * rsh[0] * c_g1 + c_be1 + sk.x;
            h1n.y = (pre.y - mush[1]) * rsh[1] * c_g1 + c_be1 + sk.y;
            h1n.z = (pre.z - mush[2]) * rsh[2] * c_g1 + c_be1 + sk.z;
            h1n.w = (pre.w - mush[3]) * rsh[3] * c_g1 + c_be1 + sk.w;
            h1s[j] = h1n;
            p1s[j] = hn;
        }
        if (tid < IN_) p0s[tid] = xts[tid];
        __syncthreads();                                            // (m)
    }

    // ---------- output head: out[b] = h1 @ Wout + bout ----------
    if (half == 0) {
        const float4 h1j = h1s[j];
        float4 part = make_float4(h1j.x * c_wout, h1j.y * c_wout,
                                  h1j.z * c_wout, h1j.w * c_wout);
        #pragma unroll
        for (int o = 16; o > 0; o >>= 1) {
            part.x += __shfl_xor_sync(0xffffffffu, part.x, o);
            part.y += __shfl_xor_sync(0xffffffffu, part.y, o);
            part.z += __shfl_xor_sync(0xffffffffu, part.z, o);
            part.w += __shfl_xor_sync(0xffffffffu, part.w, o);
        }
        if (lane == 0) redbuf[wid] = part;
    }
    __syncthreads();
    if (tid < ROWS_) {
        const float* rf = (const float*)redbuf;
        float s = c_bout;
        #pragma unroll
        for (int w = 0; w < 8; ++w) s += rf[w * 4 + tid];
        out[b0 + tid] = s;
    }
}

extern "C" void kernel_launch(void* const* d_in, const int* in_sizes, int n_in,
                              void* d_out, int out_size)
{
    (void)in_sizes; (void)n_in; (void)out_size;
    const float* x      = (const float*)d_in[0];
    const float* Win0   = (const float*)d_in[1];
    const float* bin0   = (const float*)d_in[2];
    const float* Wrec0  = (const float*)d_in[3];
    const float* brec0  = (const float*)d_in[4];
    const float* Wattn0 = (const float*)d_in[5];
    const float* battn0 = (const float*)d_in[6];
    const float* Wev0   = (const float*)d_in[7];
    const float* bev0   = (const float*)d_in[8];
    const float* tau0   = (const float*)d_in[9];
    const float* gamma0 = (const float*)d_in[10];
    const float* beta0  = (const float*)d_in[11];
    const float* Win1   = (const float*)d_in[12];
    const float* bin1   = (const float*)d_in[13];
    const float* Wrec1  = (const float*)d_in[14];
    const float* brec1  = (const float*)d_in[15];
    const float* Wattn1 = (const float*)d_in[16];
    const float* battn1 = (const float*)d_in[17];
    const float* Wev1   = (const float*)d_in[18];
    const float* bev1   = (const float*)d_in[19];
    const float* tau1   = (const float*)d_in[20];
    const float* gamma1 = (const float*)d_in[21];
    const float* beta1  = (const float*)d_in[22];
    const float* Wskip  = (const float*)d_in[23];
    const float* bskip  = (const float*)d_in[24];
    const float* Wout   = (const float*)d_in[25];
    const float* bout   = (const float*)d_in[26];

    liquid_kernel<<<NBLK_, THREADS_>>>(x,
        Win0, bin0, Wrec0, brec0, Wattn0, battn0, Wev0, bev0, tau0, gamma0, beta0,
        Win1, bin1, Wrec1, brec1, Wattn1, battn1, Wev1, bev1, tau1, gamma1, beta1,
        Wskip, bskip, Wout, bout, (float*)d_out);
}

// round 9
// speedup vs baseline: 2.1482x; 1.0699x over previous
#include <cuda_runtime.h>
#include <math.h>

#define T_   2048
#define B_   512
#define IN_  32
#define H_   256
#define ROWS_ 4
#define NBLK_ (B_ / ROWS_)
#define THREADS_ 512
#define DT_C  0.1f
#define EPS_C 1e-5f

typedef unsigned long long u64;

// Repacked fp32 weights: 6 matrices [H x H] -> [H/4][H] float4 where
// Wp[(m*64 + k4)*256 + j] = { W[(4k4+0)*H+j], W[(4k4+1)*H+j], W[(4k4+2)*H+j], W[(4k4+3)*H+j] }
// Order m: Wattn0, Wrec0, Wattn1, Win1, Wskip, Wrec1
#define MATP_ (64 * 256)
__device__ float4 g_Wp[6 * MATP_];

__device__ __forceinline__ float sigf(float z) { return 1.0f / (1.0f + expf(-z)); }

__device__ __forceinline__ u64 pack_dup(float w) {
    u64 r;
    unsigned int u = __float_as_uint(w);
    asm("mov.b64 %0, {%1, %1};" : "=l"(r) : "r"(u));
    return r;
}
__device__ __forceinline__ void unpack2(u64 v, float& a, float& b) {
    unsigned int lo, hi;
    asm("mov.b64 {%0, %1}, %2;" : "=r"(lo), "=r"(hi) : "l"(v));
    a = __uint_as_float(lo); b = __uint_as_float(hi);
}
__device__ __forceinline__ void fma2(u64& acc, u64 a, u64 b) {
    asm("fma.rn.f32x2 %0, %1, %2, %0;" : "+l"(acc) : "l"(a), "l"(b));
}

__global__ void pack_weights(const float* __restrict__ W0, const float* __restrict__ W1,
                             const float* __restrict__ W2, const float* __restrict__ W3,
                             const float* __restrict__ W4, const float* __restrict__ W5)
{
    int idx = blockIdx.x * blockDim.x + threadIdx.x;   // one float4 output
    if (idx >= 6 * MATP_) return;
    const float* Ws[6] = {W0, W1, W2, W3, W4, W5};
    int m  = idx / MATP_;
    int r  = idx - m * MATP_;
    int k4 = r >> 8;
    int j  = r & 255;
    const float* W = Ws[m];
    g_Wp[idx] = make_float4(W[(4 * k4 + 0) * H_ + j], W[(4 * k4 + 1) * H_ + j],
                            W[(4 * k4 + 2) * H_ + j], W[(4 * k4 + 3) * H_ + j]);
}

// Partial matvec over 128 k values (one K-half).
// wp: packed weight base offset to (m*64 + half*32)*256 + j ; stride H_ float4 per k4
// st: state base + half*128 (float4 = rows 0..3)
__device__ __forceinline__ float4 mv_partial(const float4* __restrict__ wp,
                                             const float4* st)
{
    u64 a01 = 0ull, a23 = 0ull;
    const ulonglong2* sp = (const ulonglong2*)st;   // sp[k] = {rows01, rows23} of st[k]
    #pragma unroll 8
    for (int k4 = 0; k4 < 32; ++k4) {
        float4 w = __ldg(&wp[k4 * H_]);
        ulonglong2 s0 = sp[4 * k4 + 0];
        ulonglong2 s1 = sp[4 * k4 + 1];
        ulonglong2 s2 = sp[4 * k4 + 2];
        ulonglong2 s3 = sp[4 * k4 + 3];
        u64 wx = pack_dup(w.x), wy = pack_dup(w.y);
        u64 wz = pack_dup(w.z), ww = pack_dup(w.w);
        fma2(a01, wx, s0.x); fma2(a23, wx, s0.y);
        fma2(a01, wy, s1.x); fma2(a23, wy, s1.y);
        fma2(a01, wz, s2.x); fma2(a23, wz, s2.y);
        fma2(a01, ww, s3.x); fma2(a23, ww, s3.y);
    }
    float4 r;
    unpack2(a01, r.x, r.y);
    unpack2(a23, r.z, r.w);
    return r;
}

// Fused 3-matrix partial matvec (attn1 from h1; inp1 & skip from h0n).
__device__ __forceinline__ void mv_partial3(const float4* __restrict__ wa,
                                            const float4* __restrict__ wi,
                                            const float4* __restrict__ ws,
                                            const float4* st_h1,
                                            const float4* st_h0n,
                                            float4& ra, float4& ri, float4& rs)
{
    u64 aa01 = 0ull, aa23 = 0ull;
    u64 ai01 = 0ull, ai23 = 0ull;
    u64 as01 = 0ull, as23 = 0ull;
    const ulonglong2* s1p = (const ulonglong2*)st_h1;
    const ulonglong2* s0p = (const ulonglong2*)st_h0n;
    #pragma unroll 4
    for (int k4 = 0; k4 < 32; ++k4) {
        float4 wA = __ldg(&wa[k4 * H_]);
        float4 wI = __ldg(&wi[k4 * H_]);
        float4 wS = __ldg(&ws[k4 * H_]);
        #pragma unroll
        for (int c = 0; c < 4; ++c) {
            ulonglong2 s1 = s1p[4 * k4 + c];
            ulonglong2 s0 = s0p[4 * k4 + c];
            float fa = (c == 0) ? wA.x : (c == 1) ? wA.y : (c == 2) ? wA.z : wA.w;
            float fi = (c == 0) ? wI.x : (c == 1) ? wI.y : (c == 2) ? wI.z : wI.w;
            float fs = (c == 0) ? wS.x : (c == 1) ? wS.y : (c == 2) ? wS.z : wS.w;
            u64 da = pack_dup(fa), di = pack_dup(fi), ds = pack_dup(fs);
            fma2(aa01, da, s1.x); fma2(aa23, da, s1.y);
            fma2(ai01, di, s0.x); fma2(ai23, di, s0.y);
            fma2(as01, ds, s0.x); fma2(as23, ds, s0.y);
        }
    }
    unpack2(aa01, ra.x, ra.y); unpack2(aa23, ra.z, ra.w);
    unpack2(ai01, ri.x, ri.y); unpack2(ai23, ri.z, ri.w);
    unpack2(as01, rs.x, rs.y); unpack2(as23, rs.z, rs.w);
}

__global__ void __launch_bounds__(THREADS_, 1)
liquid_kernel(const float* __restrict__ x,
              const float* __restrict__ Win0,  const float* __restrict__ bin0,
              const float* __restrict__ brec0,
              const float* __restrict__ battn0,
              const float* __restrict__ Wev0,  const float* __restrict__ bev0,
              const float* __restrict__ tau0,  const float* __restrict__ gamma0,
              const float* __restrict__ beta0,
              const float* __restrict__ bin1,
              const float* __restrict__ brec1,
              const float* __restrict__ battn1,
              const float* __restrict__ Wev1,  const float* __restrict__ bev1,
              const float* __restrict__ tau1,  const float* __restrict__ gamma1,
              const float* __restrict__ beta1,
              const float* __restrict__ bskip,
              const float* __restrict__ Wout,  const float* __restrict__ bout,
              float* __restrict__ out)
{
    // States packed as float4 over ROWS_=4 batch rows
    __shared__ float4 h0s[H_], h1s[H_], p1s[H_], gbuf[H_], h0ns[H_], tbuf[H_];
    __shared__ float4 pb_a[H_], pb_b[H_], pb_c[H_];      // split-K partial buffers
    __shared__ float4 xts[IN_], p0s[IN_];
    __shared__ float4 redbuf[8];
    __shared__ float  wev0s[2 * IN_];
    __shared__ float  ew0sh[ROWS_], ew1sh[ROWS_], mush[ROWS_], rsh[ROWS_];

    const int tid  = threadIdx.x;
    const int j    = tid & 255;       // feature index
    const int half = tid >> 8;        // K-split half (0/1)
    const int lane = tid & 31;
    const int wid  = tid >> 5;        // 0..15
    const int b0   = blockIdx.x * ROWS_;
    const int so   = half * 128;      // state offset (float4 units) for this half

    // ---- per-feature constants ----
    const float c_bin0 = bin0[j],  c_ba0 = battn0[j], c_br0 = brec0[j];
    const float c_bin1 = bin1[j],  c_ba1 = battn1[j], c_br1 = brec1[j];
    const float c_g0   = gamma0[j], c_be0 = beta0[j];
    const float c_g1   = gamma1[j], c_be1 = beta1[j];
    const float c_bsk  = bskip[j];
    const float rt0 = DT_C / fminf(fmaxf(tau0[j], 0.1f), 10.0f);
    const float rt1 = DT_C / fminf(fmaxf(tau1[j], 0.1f), 10.0f);
    const float wv1a = Wev1[j], wv1b = Wev1[H_ + j];
    const float c_wout = Wout[j];
    const float c_bev0 = bev0[0], c_bev1 = bev1[0], c_bout = bout[0];

    // packed weight base pointers: (m*64 + half*32)*256 + j
    const int wofs = half * 32 * H_ + j;
    const float4* Wa0 = g_Wp + 0 * MATP_ + wofs;
    const float4* Wr0 = g_Wp + 1 * MATP_ + wofs;
    const float4* Wa1 = g_Wp + 2 * MATP_ + wofs;
    const float4* Wi1 = g_Wp + 3 * MATP_ + wofs;
    const float4* Wsk = g_Wp + 4 * MATP_ + wofs;
    const float4* Wr1 = g_Wp + 5 * MATP_ + wofs;

    if (tid < 2 * IN_) wev0s[tid] = Wev0[tid];
    const float4 z4 = make_float4(0.f, 0.f, 0.f, 0.f);
    if (half == 0) { h0s[j] = z4; h1s[j] = z4; p1s[j] = z4; }
    if (tid < IN_) p0s[tid] = z4;
    __syncthreads();

    float* ew0o = out + B_;
    float* ew1o = out + B_ + (size_t)B_ * T_;

    for (int t = 0; t < T_; ++t) {
        // ---------- load x_t ----------
        if (tid < IN_) {
            float4 v;
            v.x = x[((size_t)(b0 + 0) * T_ + t) * IN_ + tid];
            v.y = x[((size_t)(b0 + 1) * T_ + t) * IN_ + tid];
            v.z = x[((size_t)(b0 + 2) * T_ + t) * IN_ + tid];
            v.w = x[((size_t)(b0 + 3) * T_ + t) * IN_ + tid];
            xts[tid] = v;
        }
        __syncthreads();                                            // (a)

        // ---------- ew0 (warps 0..3, fp32 exact) ----------
        if (wid < ROWS_) {
            const float* xf = (const float*)xts;
            const float* pf = (const float*)p0s;
            float s = xf[lane * 4 + wid] * wev0s[lane]
                    + pf[lane * 4 + wid] * wev0s[IN_ + lane];
            #pragma unroll
            for (int o = 16; o > 0; o >>= 1) s += __shfl_xor_sync(0xffffffffu, s, o);
            if (lane == 0) {
                float e = (t > 0) ? sigf(s + c_bev0) : 0.0f;
                ew0sh[wid] = e;
                ew0o[(size_t)(b0 + wid) * T_ + t] = e;
            }
        }

        // ---------- attn0 partial (both halves) + inp0 (half 0) ----------
        float4 a0p = mv_partial(Wa0, h0s + so);
        float4 i0  = make_float4(c_bin0, c_bin0, c_bin0, c_bin0);
        if (half == 0) {
            #pragma unroll
            for (int i = 0; i < IN_; ++i) {
                float w = Win0[i * H_ + j];
                float4 xv = xts[i];
                i0.x = fmaf(w, xv.x, i0.x); i0.y = fmaf(w, xv.y, i0.y);
                i0.z = fmaf(w, xv.z, i0.z); i0.w = fmaf(w, xv.w, i0.w);
            }
        } else {
            pb_a[j] = a0p;
        }
        __syncthreads();                                            // (b)

        // ---------- finalize attn0, publish gated state ----------
        float4 h0j;
        if (half == 0) {
            h0j = h0s[j];
            float4 p = pb_a[j];
            float4 a0;
            a0.x = sigf(a0p.x + p.x + c_ba0);
            a0.y = sigf(a0p.y + p.y + c_ba0);
            a0.z = sigf(a0p.z + p.z + c_ba0);
            a0.w = sigf(a0p.w + p.w + c_ba0);
            gbuf[j] = make_float4(h0j.x * a0.x, h0j.y * a0.y, h0j.z * a0.z, h0j.w * a0.w);
        }
        __syncthreads();                                            // (c)

        // ---------- rec0 partial ----------
        float4 r0p = mv_partial(Wr0, gbuf + so);
        if (half == 1) pb_a[j] = r0p;
        __syncthreads();                                            // (d)

        // ---------- pre-LN layer-0 update ----------
        float4 pre;
        if (half == 0) {
            float4 p = pb_a[j];
            float r0x = r0p.x + p.x + c_br0, r0y = r0p.y + p.y + c_br0;
            float r0z = r0p.z + p.z + c_br0, r0w = r0p.w + p.w + c_br0;
            const float e0 = 1.f + ew0sh[0], e1 = 1.f + ew0sh[1];
            const float e2 = 1.f + ew0sh[2], e3 = 1.f + ew0sh[3];
            pre.x = h0j.x + rt0 * (-h0j.x + tanhf(i0.x) + tanhf(r0x)) * e0;
            pre.y = h0j.y + rt0 * (-h0j.y + tanhf(i0.y) + tanhf(r0y)) * e1;
            pre.z = h0j.z + rt0 * (-h0j.z + tanhf(i0.z) + tanhf(r0z)) * e2;
            pre.w = h0j.w + rt0 * (-h0j.w + tanhf(i0.w) + tanhf(r0w)) * e3;
            tbuf[j] = pre;
        }
        __syncthreads();                                            // (e)

        // ---------- LN0 stats (warp per row) ----------
        if (wid < ROWS_) {
            const float* tf = (const float*)tbuf;
            float s = 0.f, ss = 0.f;
            #pragma unroll
            for (int m = 0; m < H_ / 32; ++m) {
                float v = tf[(lane + 32 * m) * 4 + wid];
                s += v; ss += v * v;
            }
            #pragma unroll
            for (int o = 16; o > 0; o >>= 1) {
                s  += __shfl_xor_sync(0xffffffffu, s, o);
                ss += __shfl_xor_sync(0xffffffffu, ss, o);
            }
            if (lane == 0) {
                float mu = s * (1.0f / H_);
                float var = ss * (1.0f / H_) - mu * mu;
                mush[wid] = mu;
                rsh[wid] = rsqrtf(var + EPS_C);
            }
        }
        __syncthreads();                                            // (f)

        // ---------- h0n = LN(pre); publish; ew1 warp partials ----------
        float4 hn;
        if (half == 0) {
            hn.x = (pre.x - mush[0]) * rsh[0] * c_g0 + c_be0;
            hn.y = (pre.y - mush[1]) * rsh[1] * c_g0 + c_be0;
            hn.z = (pre.z - mush[2]) * rsh[2] * c_g0 + c_be0;
            hn.w = (pre.w - mush[3]) * rsh[3] * c_g0 + c_be0;
            h0ns[j] = hn;
            h0s[j]  = hn;
            const float4 pv = p1s[j];
            float4 part;
            part.x = hn.x * wv1a + pv.x * wv1b;
            part.y = hn.y * wv1a + pv.y * wv1b;
            part.z = hn.z * wv1a + pv.z * wv1b;
            part.w = hn.w * wv1a + pv.w * wv1b;
            #pragma unroll
            for (int o = 16; o > 0; o >>= 1) {
                part.x += __shfl_xor_sync(0xffffffffu, part.x, o);
                part.y += __shfl_xor_sync(0xffffffffu, part.y, o);
                part.z += __shfl_xor_sync(0xffffffffu, part.z, o);
                part.w += __shfl_xor_sync(0xffffffffu, part.w, o);
            }
            if (lane == 0) redbuf[wid] = part;
        }
        __syncthreads();                                            // (g)

        if (tid < ROWS_) {
            const float* rf = (const float*)redbuf;
            float s = c_bev1;
            #pragma unroll
            for (int w = 0; w < 8; ++w) s += rf[w * 4 + tid];
            float e = (t > 0) ? sigf(s) : 0.0f;
            ew1sh[tid] = e;
            ew1o[(size_t)(b0 + tid) * T_ + t] = e;
        }

        // ---------- attn1 / inp1 / skip partials (both halves, fused) ----------
        float4 a1p, i1p, skp;
        mv_partial3(Wa1, Wi1, Wsk, h1s + so, h0ns + so, a1p, i1p, skp);
        if (half == 1) { pb_a[j] = a1p; pb_b[j] = i1p; pb_c[j] = skp; }
        __syncthreads();                                            // (h)

        float4 h1j, i1, sk;
        if (half == 0) {
            h1j = h1s[j];
            float4 pa = pb_a[j], pi = pb_b[j], ps = pb_c[j];
            float4 a1;
            a1.x = sigf(a1p.x + pa.x + c_ba1);
            a1.y = sigf(a1p.y + pa.y + c_ba1);
            a1.z = sigf(a1p.z + pa.z + c_ba1);
            a1.w = sigf(a1p.w + pa.w + c_ba1);
            i1 = make_float4(i1p.x + pi.x + c_bin1, i1p.y + pi.y + c_bin1,
                             i1p.z + pi.z + c_bin1, i1p.w + pi.w + c_bin1);
            sk = make_float4(skp.x + ps.x + c_bsk, skp.y + ps.y + c_bsk,
                             skp.z + ps.z + c_bsk, skp.w + ps.w + c_bsk);
            gbuf[j] = make_float4(h1j.x * a1.x, h1j.y * a1.y, h1j.z * a1.z, h1j.w * a1.w);
        }
        __syncthreads();                                            // (i)

        // ---------- rec1 partial ----------
        float4 r1p = mv_partial(Wr1, gbuf + so);
        if (half == 1) pb_a[j] = r1p;
        __syncthreads();                                            // (j)

        if (half == 0) {
            float4 p = pb_a[j];
            float r1x = r1p.x + p.x + c_br1, r1y = r1p.y + p.y + c_br1;
            float r1z = r1p.z + p.z + c_br1, r1w = r1p.w + p.w + c_br1;
            const float e0 = 1.f + ew1sh[0], e1 = 1.f + ew1sh[1];
            const float e2 = 1.f + ew1sh[2], e3 = 1.f + ew1sh[3];
            pre.x = h1j.x + rt1 * (-h1j.x + tanhf(i1.x) + tanhf(r1x)) * e0;
            pre.y = h1j.y + rt1 * (-h1j.y + tanhf(i1.y) + tanhf(r1y)) * e1;
            pre.z = h1j.z + rt1 * (-h1j.z + tanhf(i1.z) + tanhf(r1z)) * e2;
            pre.w = h1j.w + rt1 * (-h1j.w + tanhf(i1.w) + tanhf(r1w)) * e3;
            tbuf[j] = pre;
        }
        __syncthreads();                                            // (k)

        // ---------- LN1 stats ----------
        if (wid < ROWS_) {
            const float* tf = (const float*)tbuf;
            float s = 0.f, ss = 0.f;
            #pragma unroll
            for (int m = 0; m < H_ / 32; ++m) {
                float v = tf[(lane + 32 * m) * 4 + wid];
                s += v; ss += v * v;
            }
            #pragma unroll
            for (int o = 16; o > 0; o >>= 1) {
                s  += __shfl_xor_sync(0xffffffffu, s, o);
                ss += __shfl_xor_sync(0xffffffffu, ss, o);
            }
            if (lane == 0) {
                float mu = s * (1.0f / H_);
                float var = ss * (1.0f / H_) - mu * mu;
                mush[wid] = mu;
                rsh[wid] = rsqrtf(var + EPS_C);
            }
        }
        __syncthreads();                                            // (l)

        // ---------- finalize states ----------
        if (half == 0) {
            float4 h1n;
            h1n.x = (pre.x - mush[0]) * rsh[0] * c_g1 + c_be1 + sk.x;
            h1n.y = (pre.y - mush[1]) * rsh[1] * c_g1 + c_be1 + sk.y;
            h1n.z = (pre.z - mush[2]) * rsh[2] * c_g1 + c_be1 + sk.z;
            h1n.w = (pre.w - mush[3]) * rsh[3] * c_g1 + c_be1 + sk.w;
            h1s[j] = h1n;
            p1s[j] = hn;
        }
        if (tid < IN_) p0s[tid] = xts[tid];
        __syncthreads();                                            // (m)
    }

    // ---------- output head: out[b] = h1 @ Wout + bout ----------
    if (half == 0) {
        const float4 h1j = h1s[j];
        float4 part = make_float4(h1j.x * c_wout, h1j.y * c_wout,
                                  h1j.z * c_wout, h1j.w * c_wout);
        #pragma unroll
        for (int o = 16; o > 0; o >>= 1) {
            part.x += __shfl_xor_sync(0xffffffffu, part.x, o);
            part.y += __shfl_xor_sync(0xffffffffu, part.y, o);
            part.z += __shfl_xor_sync(0xffffffffu, part.z, o);
            part.w += __shfl_xor_sync(0xffffffffu, part.w, o);
        }
        if (lane == 0) redbuf[wid] = part;
    }
    __syncthreads();
    if (tid < ROWS_) {
        const float* rf = (const float*)redbuf;
        float s = c_bout;
        #pragma unroll
        for (int w = 0; w < 8; ++w) s += rf[w * 4 + tid];
        out[b0 + tid] = s;
    }
}

extern "C" void kernel_launch(void* const* d_in, const int* in_sizes, int n_in,
                              void* d_out, int out_size)
{
    (void)in_sizes; (void)n_in; (void)out_size;
    const float* x      = (const float*)d_in[0];
    const float* Win0   = (const float*)d_in[1];
    const float* bin0   = (const float*)d_in[2];
    const float* Wrec0  = (const float*)d_in[3];
    const float* brec0  = (const float*)d_in[4];
    const float* Wattn0 = (const float*)d_in[5];
    const float* battn0 = (const float*)d_in[6];
    const float* Wev0   = (const float*)d_in[7];
    const float* bev0   = (const float*)d_in[8];
    const float* tau0   = (const float*)d_in[9];
    const float* gamma0 = (const float*)d_in[10];
    const float* beta0  = (const float*)d_in[11];
    const float* Win1   = (const float*)d_in[12];
    const float* bin1   = (const float*)d_in[13];
    const float* Wrec1  = (const float*)d_in[14];
    const float* brec1  = (const float*)d_in[15];
    const float* Wattn1 = (const float*)d_in[16];
    const float* battn1 = (const float*)d_in[17];
    const float* Wev1   = (const float*)d_in[18];
    const float* bev1   = (const float*)d_in[19];
    const float* tau1   = (const float*)d_in[20];
    const float* gamma1 = (const float*)d_in[21];
    const float* beta1  = (const float*)d_in[22];
    const float* Wskip  = (const float*)d_in[23];
    const float* bskip  = (const float*)d_in[24];
    const float* Wout   = (const float*)d_in[25];
    const float* bout   = (const float*)d_in[26];

    // Repack the six HxH fp32 matrices into k4-vectorized layout (exact fp32 copy).
    pack_weights<<<(6 * MATP_ + 255) / 256, 256>>>(
        Wattn0, Wrec0, Wattn1, Win1, Wskip, Wrec1);

    liquid_kernel<<<NBLK_, THREADS_>>>(x,
        Win0, bin0, brec0, battn0, Wev0, bev0, tau0, gamma0, beta0,
        bin1, brec1, battn1, Wev1, bev1, tau1, gamma1, beta1,
        bskip, Wout, bout, (float*)d_out);
}

// round 11
// speedup vs baseline: 2.7228x; 1.2675x over previous
#include <cuda_runtime.h>
#include <math.h>

#define T_   2048
#define B_   512
#define IN_  32
#define H_   256
#define ROWS_ 4
#define NBLK_ (B_ / ROWS_)
#define THREADS_ 512
#define DT_C  0.1f
#define EPS_C 1e-5f

typedef unsigned long long u64;

// Repacked fp32 weights: 6 matrices [H x H] -> [H/4][H] float4:
// g_Wp[(m*64 + k4)*256 + j] = { W[4k4+0][j], W[4k4+1][j], W[4k4+2][j], W[4k4+3][j] }
// Order m: Wattn0, Wrec0, Wattn1, Win1, Wskip, Wrec1
#define MATP_ (64 * 256)
__device__ float4 g_Wp[6 * MATP_];

// Dynamic SMEM layout (float4 units):
//  [0,256)      h0s      [256,512)   h1s     [512,768)   p1s
//  [768,1024)   gbuf     [1024,1280) h0ns    [1280,1536) tbuf
//  [1536,4608)  pb[4][3][256]
//  [4608,4640)  xts      [4640,4672) p0s     [4672,4680) redbuf
//  then floats: params[16][256], wev0s[64], scal[16]
#define SMEM_BYTES_ (4680 * 16 + 4096 * 4 + 64 * 4 + 16 * 4)

__device__ __forceinline__ float sigf(float z) { return 1.0f / (1.0f + expf(-z)); }

__device__ __forceinline__ u64 pack_dup(float w) {
    u64 r;
    unsigned int u = __float_as_uint(w);
    asm("mov.b64 %0, {%1, %1};" : "=l"(r) : "r"(u));
    return r;
}
__device__ __forceinline__ void unpack2(u64 v, float& a, float& b) {
    unsigned int lo, hi;
    asm("mov.b64 {%0, %1}, %2;" : "=r"(lo), "=r"(hi) : "l"(v));
    a = __uint_as_float(lo); b = __uint_as_float(hi);
}
__device__ __forceinline__ void fma2(u64& acc, u64 a, u64 b) {
    asm("fma.rn.f32x2 %0, %1, %2, %0;" : "+l"(acc) : "l"(a), "l"(b));
}

__global__ void pack_weights(const float* __restrict__ W0, const float* __restrict__ W1,
                             const float* __restrict__ W2, const float* __restrict__ W3,
                             const float* __restrict__ W4, const float* __restrict__ W5)
{
    int idx = blockIdx.x * blockDim.x + threadIdx.x;
    if (idx >= 6 * MATP_) return;
    const float* Ws[6] = {W0, W1, W2, W3, W4, W5};
    int m  = idx / MATP_;
    int r  = idx - m * MATP_;
    int k4 = r >> 8;
    int j  = r & 255;
    const float* W = Ws[m];
    g_Wp[idx] = make_float4(W[(4 * k4 + 0) * H_ + j], W[(4 * k4 + 1) * H_ + j],
                            W[(4 * k4 + 2) * H_ + j], W[(4 * k4 + 3) * H_ + j]);
}

// Quarter-K (64 k) matvec partial, 2 output columns, shared state loads.
__device__ __forceinline__ void mv2(const float4* __restrict__ wp0,
                                    const float4* __restrict__ wp1,
                                    const float4* st, float4& rA, float4& rB)
{
    u64 a01 = 0ull, a23 = 0ull, b01 = 0ull, b23 = 0ull;
    const ulonglong2* sp = (const ulonglong2*)st;
    #pragma unroll
    for (int k4 = 0; k4 < 16; ++k4) {
        float4 wA = __ldg(&wp0[k4 * H_]);
        float4 wB = __ldg(&wp1[k4 * H_]);
        ulonglong2 s0 = sp[4 * k4 + 0];
        ulonglong2 s1 = sp[4 * k4 + 1];
        ulonglong2 s2 = sp[4 * k4 + 2];
        ulonglong2 s3 = sp[4 * k4 + 3];
        u64 d;
        d = pack_dup(wA.x); fma2(a01, d, s0.x); fma2(a23, d, s0.y);
        d = pack_dup(wB.x); fma2(b01, d, s0.x); fma2(b23, d, s0.y);
        d = pack_dup(wA.y); fma2(a01, d, s1.x); fma2(a23, d, s1.y);
        d = pack_dup(wB.y); fma2(b01, d, s1.x); fma2(b23, d, s1.y);
        d = pack_dup(wA.z); fma2(a01, d, s2.x); fma2(a23, d, s2.y);
        d = pack_dup(wB.z); fma2(b01, d, s2.x); fma2(b23, d, s2.y);
        d = pack_dup(wA.w); fma2(a01, d, s3.x); fma2(a23, d, s3.y);
        d = pack_dup(wB.w); fma2(b01, d, s3.x); fma2(b23, d, s3.y);
    }
    unpack2(a01, rA.x, rA.y); unpack2(a23, rA.z, rA.w);
    unpack2(b01, rB.x, rB.y); unpack2(b23, rB.z, rB.w);
}

// Two matrices over the same state vector, 2 columns each (inp1 + skip).
__device__ __forceinline__ void mv2pair(const float4* __restrict__ wi0,
                                        const float4* __restrict__ wi1,
                                        const float4* __restrict__ ws0,
                                        const float4* __restrict__ ws1,
                                        const float4* st,
                                        float4& riA, float4& riB,
                                        float4& rsA, float4& rsB)
{
    u64 ia01 = 0ull, ia23 = 0ull, ib01 = 0ull, ib23 = 0ull;
    u64 sa01 = 0ull, sa23 = 0ull, sb01 = 0ull, sb23 = 0ull;
    const ulonglong2* sp = (const ulonglong2*)st;
    #pragma unroll
    for (int k4 = 0; k4 < 16; ++k4) {
        float4 wIA = __ldg(&wi0[k4 * H_]);
        float4 wIB = __ldg(&wi1[k4 * H_]);
        float4 wSA = __ldg(&ws0[k4 * H_]);
        float4 wSB = __ldg(&ws1[k4 * H_]);
        ulonglong2 s0 = sp[4 * k4 + 0];
        ulonglong2 s1 = sp[4 * k4 + 1];
        ulonglong2 s2 = sp[4 * k4 + 2];
        ulonglong2 s3 = sp[4 * k4 + 3];
        u64 d;
        d = pack_dup(wIA.x); fma2(ia01, d, s0.x); fma2(ia23, d, s0.y);
        d = pack_dup(wIB.x); fma2(ib01, d, s0.x); fma2(ib23, d, s0.y);
        d = pack_dup(wSA.x); fma2(sa01, d, s0.x); fma2(sa23, d, s0.y);
        d = pack_dup(wSB.x); fma2(sb01, d, s0.x); fma2(sb23, d, s0.y);
        d = pack_dup(wIA.y); fma2(ia01, d, s1.x); fma2(ia23, d, s1.y);
        d = pack_dup(wIB.y); fma2(ib01, d, s1.x); fma2(ib23, d, s1.y);
        d = pack_dup(wSA.y); fma2(sa01, d, s1.x); fma2(sa23, d, s1.y);
        d = pack_dup(wSB.y); fma2(sb01, d, s1.x); fma2(sb23, d, s1.y);
        d = pack_dup(wIA.z); fma2(ia01, d, s2.x); fma2(ia23, d, s2.y);
        d = pack_dup(wIB.z); fma2(ib01, d, s2.x); fma2(ib23, d, s2.y);
        d = pack_dup(wSA.z); fma2(sa01, d, s2.x); fma2(sa23, d, s2.y);
        d = pack_dup(wSB.z); fma2(sb01, d, s2.x); fma2(sb23, d, s2.y);
        d = pack_dup(wIA.w); fma2(ia01, d, s3.x); fma2(ia23, d, s3.y);
        d = pack_dup(wIB.w); fma2(ib01, d, s3.x); fma2(ib23, d, s3.y);
        d = pack_dup(wSA.w); fma2(sa01, d, s3.x); fma2(sa23, d, s3.y);
        d = pack_dup(wSB.w); fma2(sb01, d, s3.x); fma2(sb23, d, s3.y);
    }
    unpack2(ia01, riA.x, riA.y); unpack2(ia23, riA.z, riA.w);
    unpack2(ib01, riB.x, riB.y); unpack2(ib23, riB.z, riB.w);
    unpack2(sa01, rsA.x, rsA.y); unpack2(sa23, rsA.z, rsA.w);
    unpack2(sb01, rsB.x, rsB.y); unpack2(sb23, rsB.z, rsB.w);
}

__global__ void __launch_bounds__(THREADS_, 1)
liquid_kernel(const float* __restrict__ x,
              const float* __restrict__ Win0,  const float* __restrict__ bin0,
              const float* __restrict__ brec0, const float* __restrict__ battn0,
              const float* __restrict__ Wev0,  const float* __restrict__ bev0,
              const float* __restrict__ tau0,  const float* __restrict__ gamma0,
              const float* __restrict__ beta0,
              const float* __restrict__ bin1,  const float* __restrict__ brec1,
              const float* __restrict__ battn1,
              const float* __restrict__ Wev1,  const float* __restrict__ bev1,
              const float* __restrict__ tau1,  const float* __restrict__ gamma1,
              const float* __restrict__ beta1,
              const float* __restrict__ bskip,
              const float* __restrict__ Wout,  const float* __restrict__ bout,
              float* __restrict__ out)
{
    extern __shared__ float4 smem4[];
    float4* h0s  = smem4;
    float4* h1s  = smem4 + 256;
    float4* p1s  = smem4 + 512;
    float4* gbuf = smem4 + 768;
    float4* h0ns = smem4 + 1024;
    float4* tbuf = smem4 + 1280;
    float4* pb   = smem4 + 1536;           // [4][3][256]
    float4* xts  = smem4 + 4608;           // 32
    float4* p0s  = smem4 + 4640;           // 32
    float4* redbuf = smem4 + 4672;         // 8
    float*  params = (float*)(smem4 + 4680);  // 16*256
    float*  wev0s  = params + 4096;           // 64
    float*  scal   = wev0s + 64;              // ew0[4], ew1[4], mu[4], rs[4]

    const int tid  = threadIdx.x;
    const int lane = tid & 31;
    const int wid  = tid >> 5;
    const int q    = tid >> 7;        // K quarter 0..3
    const int jp   = tid & 127;       // column pair index
    const int j0   = jp, j1 = jp + 128;
    const int b0   = blockIdx.x * ROWS_;

    const float c_bev0 = bev0[0], c_bev1 = bev1[0], c_bout = bout[0];

    // weight bases: matrix m, quarter q, cols j0/j1
    const int qofs = q * 16 * H_;
    const float4* Wa0_0 = g_Wp + 0 * MATP_ + qofs + j0;
    const float4* Wa0_1 = g_Wp + 0 * MATP_ + qofs + j1;
    const float4* Wr0_0 = g_Wp + 1 * MATP_ + qofs + j0;
    const float4* Wr0_1 = g_Wp + 1 * MATP_ + qofs + j1;
    const float4* Wa1_0 = g_Wp + 2 * MATP_ + qofs + j0;
    const float4* Wa1_1 = g_Wp + 2 * MATP_ + qofs + j1;
    const float4* Wi1_0 = g_Wp + 3 * MATP_ + qofs + j0;
    const float4* Wi1_1 = g_Wp + 3 * MATP_ + qofs + j1;
    const float4* Wsk_0 = g_Wp + 4 * MATP_ + qofs + j0;
    const float4* Wsk_1 = g_Wp + 4 * MATP_ + qofs + j1;
    const float4* Wr1_0 = g_Wp + 5 * MATP_ + qofs + j0;
    const float4* Wr1_1 = g_Wp + 5 * MATP_ + qofs + j1;

    const float4 z4 = make_float4(0.f, 0.f, 0.f, 0.f);
    if (tid < 256) {
        int j = tid;
        params[0 * 256 + j]  = battn0[j];
        params[1 * 256 + j]  = brec0[j];
        params[2 * 256 + j]  = bin0[j];
        params[3 * 256 + j]  = battn1[j];
        params[4 * 256 + j]  = brec1[j];
        params[5 * 256 + j]  = bin1[j];
        params[6 * 256 + j]  = bskip[j];
        params[7 * 256 + j]  = gamma0[j];
        params[8 * 256 + j]  = beta0[j];
        params[9 * 256 + j]  = gamma1[j];
        params[10 * 256 + j] = beta1[j];
        params[11 * 256 + j] = DT_C / fminf(fmaxf(tau0[j], 0.1f), 10.0f);
        params[12 * 256 + j] = DT_C / fminf(fmaxf(tau1[j], 0.1f), 10.0f);
        params[13 * 256 + j] = Wev1[j];
        params[14 * 256 + j] = Wev1[H_ + j];
        params[15 * 256 + j] = Wout[j];
        h0s[j] = z4; h1s[j] = z4; p1s[j] = z4;
    }
    if (tid < 2 * IN_) wev0s[tid] = Wev0[tid];
    if (tid < IN_) p0s[tid] = z4;
    __syncthreads();

    float* ew0o = out + B_;
    float* ew1o = out + B_ + (size_t)B_ * T_;

    // persistent per-j registers for epilogue threads (tid<256)
    float4 i0 = z4, pre = z4, hn = z4, h1j = z4, pre1 = z4, skv = z4;

    for (int t = 0; t < T_; ++t) {
        // ---------- (a) load x_t ----------
        if (tid < IN_) {
            float4 v;
            v.x = x[((size_t)(b0 + 0) * T_ + t) * IN_ + tid];
            v.y = x[((size_t)(b0 + 1) * T_ + t) * IN_ + tid];
            v.z = x[((size_t)(b0 + 2) * T_ + t) * IN_ + tid];
            v.w = x[((size_t)(b0 + 3) * T_ + t) * IN_ + tid];
            xts[tid] = v;
        }
        __syncthreads();

        // ---------- (b) ew0 + attn0 partials + i0 ----------
        if (wid < ROWS_) {
            const float* xf = (const float*)xts;
            const float* pf = (const float*)p0s;
            float s = xf[lane * 4 + wid] * wev0s[lane]
                    + pf[lane * 4 + wid] * wev0s[IN_ + lane];
            #pragma unroll
            for (int o = 16; o > 0; o >>= 1) s += __shfl_xor_sync(0xffffffffu, s, o);
            if (lane == 0) {
                float e = (t > 0) ? sigf(s + c_bev0) : 0.0f;
                scal[wid] = e;
                ew0o[(size_t)(b0 + wid) * T_ + t] = e;
            }
        }
        {
            float4 pA, pB;
            mv2(Wa0_0, Wa0_1, h0s + q * 64, pA, pB);
            pb[(q * 3 + 0) * 256 + j0] = pA;
            pb[(q * 3 + 0) * 256 + j1] = pB;
        }
        if (tid < 256) {
            int j = tid;
            float bi = params[2 * 256 + j];
            i0 = make_float4(bi, bi, bi, bi);
            #pragma unroll
            for (int i = 0; i < IN_; ++i) {
                float w = Win0[i * H_ + j];
                float4 xv = xts[i];
                i0.x = fmaf(w, xv.x, i0.x); i0.y = fmaf(w, xv.y, i0.y);
                i0.z = fmaf(w, xv.z, i0.z); i0.w = fmaf(w, xv.w, i0.w);
            }
        }
        __syncthreads();

        // ---------- (c) finalize attn0, publish gated state ----------
        if (tid < 256) {
            int j = tid;
            float4 s0 = pb[j], s1 = pb[768 + j], s2 = pb[1536 + j], s3 = pb[2304 + j];
            float ba = params[0 * 256 + j];
            float4 a0;
            a0.x = sigf(s0.x + s1.x + s2.x + s3.x + ba);
            a0.y = sigf(s0.y + s1.y + s2.y + s3.y + ba);
            a0.z = sigf(s0.z + s1.z + s2.z + s3.z + ba);
            a0.w = sigf(s0.w + s1.w + s2.w + s3.w + ba);
            float4 h0j = h0s[j];
            gbuf[j] = make_float4(h0j.x * a0.x, h0j.y * a0.y, h0j.z * a0.z, h0j.w * a0.w);
        }
        __syncthreads();

        // ---------- (d) rec0 partials ----------
        {
            float4 pA, pB;
            mv2(Wr0_0, Wr0_1, gbuf + q * 64, pA, pB);
            pb[(q * 3 + 0) * 256 + j0] = pA;
            pb[(q * 3 + 0) * 256 + j1] = pB;
        }
        __syncthreads();

        // ---------- (e) pre-LN layer-0 update ----------
        if (tid < 256) {
            int j = tid;
            float4 s0 = pb[j], s1 = pb[768 + j], s2 = pb[1536 + j], s3 = pb[2304 + j];
            float br = params[1 * 256 + j];
            float r0x = s0.x + s1.x + s2.x + s3.x + br;
            float r0y = s0.y + s1.y + s2.y + s3.y + br;
            float r0z = s0.z + s1.z + s2.z + s3.z + br;
            float r0w = s0.w + s1.w + s2.w + s3.w + br;
            float4 h0j = h0s[j];
            float rt0 = params[11 * 256 + j];
            const float e0 = 1.f + scal[0], e1 = 1.f + scal[1];
            const float e2 = 1.f + scal[2], e3 = 1.f + scal[3];
            pre.x = h0j.x + rt0 * (-h0j.x + tanhf(i0.x) + tanhf(r0x)) * e0;
            pre.y = h0j.y + rt0 * (-h0j.y + tanhf(i0.y) + tanhf(r0y)) * e1;
            pre.z = h0j.z + rt0 * (-h0j.z + tanhf(i0.z) + tanhf(r0z)) * e2;
            pre.w = h0j.w + rt0 * (-h0j.w + tanhf(i0.w) + tanhf(r0w)) * e3;
            tbuf[j] = pre;
        }
        __syncthreads();

        // ---------- (f) LN0 stats ----------
        if (wid < ROWS_) {
            const float* tf = (const float*)tbuf;
            float s = 0.f, ss = 0.f;
            #pragma unroll
            for (int m = 0; m < H_ / 32; ++m) {
                float v = tf[(lane + 32 * m) * 4 + wid];
                s += v; ss += v * v;
            }
            #pragma unroll
            for (int o = 16; o > 0; o >>= 1) {
                s  += __shfl_xor_sync(0xffffffffu, s, o);
                ss += __shfl_xor_sync(0xffffffffu, ss, o);
            }
            if (lane == 0) {
                float mu = s * (1.0f / H_);
                float var = ss * (1.0f / H_) - mu * mu;
                scal[8 + wid]  = mu;
                scal[12 + wid] = rsqrtf(var + EPS_C);
            }
        }
        __syncthreads();

        // ---------- (g) h0n = LN(pre); ew1 partials ----------
        if (tid < 256) {
            int j = tid;
            float g0 = params[7 * 256 + j], be0 = params[8 * 256 + j];
            hn.x = (pre.x - scal[8])  * scal[12] * g0 + be0;
            hn.y = (pre.y - scal[9])  * scal[13] * g0 + be0;
            hn.z = (pre.z - scal[10]) * scal[14] * g0 + be0;
            hn.w = (pre.w - scal[11]) * scal[15] * g0 + be0;
            h0ns[j] = hn;
            h0s[j]  = hn;
            float4 pv = p1s[j];
            float wa = params[13 * 256 + j], wb = params[14 * 256 + j];
            float4 part;
            part.x = hn.x * wa + pv.x * wb;
            part.y = hn.y * wa + pv.y * wb;
            part.z = hn.z * wa + pv.z * wb;
            part.w = hn.w * wa + pv.w * wb;
            #pragma unroll
            for (int o = 16; o > 0; o >>= 1) {
                part.x += __shfl_xor_sync(0xffffffffu, part.x, o);
                part.y += __shfl_xor_sync(0xffffffffu, part.y, o);
                part.z += __shfl_xor_sync(0xffffffffu, part.z, o);
                part.w += __shfl_xor_sync(0xffffffffu, part.w, o);
            }
            if (lane == 0) redbuf[wid] = part;
        }
        __syncthreads();

        // ---------- (h) ew1 final + attn1 partials ----------
        if (tid < ROWS_) {
            const float* rf = (const float*)redbuf;
            float s = c_bev1;
            #pragma unroll
            for (int w = 0; w < 8; ++w) s += rf[w * 4 + tid];
            float e = (t > 0) ? sigf(s) : 0.0f;
            scal[4 + tid] = e;
            ew1o[(size_t)(b0 + tid) * T_ + t] = e;
        }
        {
            float4 pA, pB;
            mv2(Wa1_0, Wa1_1, h1s + q * 64, pA, pB);
            pb[(q * 3 + 0) * 256 + j0] = pA;
            pb[(q * 3 + 0) * 256 + j1] = pB;
        }
        __syncthreads();

        // ---------- (i) finalize attn1, publish gated state ----------
        if (tid < 256) {
            int j = tid;
            float4 s0 = pb[j], s1 = pb[768 + j], s2 = pb[1536 + j], s3 = pb[2304 + j];
            float ba = params[3 * 256 + j];
            float4 a1;
            a1.x = sigf(s0.x + s1.x + s2.x + s3.x + ba);
            a1.y = sigf(s0.y + s1.y + s2.y + s3.y + ba);
            a1.z = sigf(s0.z + s1.z + s2.z + s3.z + ba);
            a1.w = sigf(s0.w + s1.w + s2.w + s3.w + ba);
            h1j = h1s[j];
            gbuf[j] = make_float4(h1j.x * a1.x, h1j.y * a1.y, h1j.z * a1.z, h1j.w * a1.w);
        }
        __syncthreads();

        // ---------- (j) inp1 + skip + rec1 partials ----------
        {
            float4 iA, iB, sA, sB;
            mv2pair(Wi1_0, Wi1_1, Wsk_0, Wsk_1, h0ns + q * 64, iA, iB, sA, sB);
            float4 rA, rB;
            mv2(Wr1_0, Wr1_1, gbuf + q * 64, rA, rB);
            pb[(q * 3 + 0) * 256 + j0] = iA;
            pb[(q * 3 + 0) * 256 + j1] = iB;
            pb[(q * 3 + 1) * 256 + j0] = sA;
            pb[(q * 3 + 1) * 256 + j1] = sB;
            pb[(q * 3 + 2) * 256 + j0] = rA;
            pb[(q * 3 + 2) * 256 + j1] = rB;
        }
        __syncthreads();

        // ---------- (k) combine; pre-LN layer-1 update ----------
        if (tid < 256) {
            int j = tid;
            float4 i0q = pb[0 * 256 + j],    i1q = pb[768 + j];
            float4 i2q = pb[1536 + j],       i3q = pb[2304 + j];
            float4 s0q = pb[256 + j],        s1q = pb[1024 + j];
            float4 s2q = pb[1792 + j],       s3q = pb[2560 + j];
            float4 r0q = pb[512 + j],        r1q = pb[1280 + j];
            float4 r2q = pb[2048 + j],       r3q = pb[2816 + j];
            float bi = params[5 * 256 + j];
            float bs = params[6 * 256 + j];
            float br = params[4 * 256 + j];
            float4 i1v;
            i1v.x = i0q.x + i1q.x + i2q.x + i3q.x + bi;
            i1v.y = i0q.y + i1q.y + i2q.y + i3q.y + bi;
            i1v.z = i0q.z + i1q.z + i2q.z + i3q.z + bi;
            i1v.w = i0q.w + i1q.w + i2q.w + i3q.w + bi;
            skv.x = s0q.x + s1q.x + s2q.x + s3q.x + bs;
            skv.y = s0q.y + s1q.y + s2q.y + s3q.y + bs;
            skv.z = s0q.z + s1q.z + s2q.z + s3q.z + bs;
            skv.w = s0q.w + s1q.w + s2q.w + s3q.w + bs;
            float r1x = r0q.x + r1q.x + r2q.x + r3q.x + br;
            float r1y = r0q.y + r1q.y + r2q.y + r3q.y + br;
            float r1z = r0q.z + r1q.z + r2q.z + r3q.z + br;
            float r1w = r0q.w + r1q.w + r2q.w + r3q.w + br;
            float rt1 = params[12 * 256 + j];
            const float e0 = 1.f + scal[4], e1 = 1.f + scal[5];
            const float e2 = 1.f + scal[6], e3 = 1.f + scal[7];
            pre1.x = h1j.x + rt1 * (-h1j.x + tanhf(i1v.x) + tanhf(r1x)) * e0;
            pre1.y = h1j.y + rt1 * (-h1j.y + tanhf(i1v.y) + tanhf(r1y)) * e1;
            pre1.z = h1j.z + rt1 * (-h1j.z + tanhf(i1v.z) + tanhf(r1z)) * e2;
            pre1.w = h1j.w + rt1 * (-h1j.w + tanhf(i1v.w) + tanhf(r1w)) * e3;
            tbuf[j] = pre1;
        }
        __syncthreads();

        // ---------- (l) LN1 stats ----------
        if (wid < ROWS_) {
            const float* tf = (const float*)tbuf;
            float s = 0.f, ss = 0.f;
            #pragma unroll
            for (int m = 0; m < H_ / 32; ++m) {
                float v = tf[(lane + 32 * m) * 4 + wid];
                s += v; ss += v * v;
            }
            #pragma unroll
            for (int o = 16; o > 0; o >>= 1) {
                s  += __shfl_xor_sync(0xffffffffu, s, o);
                ss += __shfl_xor_sync(0xffffffffu, ss, o);
            }
            if (lane == 0) {
                float mu = s * (1.0f / H_);
                float var = ss * (1.0f / H_) - mu * mu;
                scal[8 + wid]  = mu;
                scal[12 + wid] = rsqrtf(var + EPS_C);
            }
        }
        __syncthreads();

        // ---------- (m) finalize states ----------
        if (tid < 256) {
            int j = tid;
            float g1 = params[9 * 256 + j], be1 = params[10 * 256 + j];
            float4 h1n;
            h1n.x = (pre1.x - scal[8])  * scal[12] * g1 + be1 + skv.x;
            h1n.y = (pre1.y - scal[9])  * scal[13] * g1 + be1 + skv.y;
            h1n.z = (pre1.z - scal[10]) * scal[14] * g1 + be1 + skv.z;
            h1n.w = (pre1.w - scal[11]) * scal[15] * g1 + be1 + skv.w;
            h1s[j] = h1n;
            p1s[j] = hn;
        }
        if (tid < IN_) p0s[tid] = xts[tid];
        __syncthreads();
    }

    // ---------- output head ----------
    if (tid < 256) {
        int j = tid;
        float wo = params[15 * 256 + j];
        float4 h = h1s[j];
        float4 part = make_float4(h.x * wo, h.y * wo, h.z * wo, h.w * wo);
        #pragma unroll
        for (int o = 16; o > 0; o >>= 1) {
            part.x += __shfl_xor_sync(0xffffffffu, part.x, o);
            part.y += __shfl_xor_sync(0xffffffffu, part.y, o);
            part.z += __shfl_xor_sync(0xffffffffu, part.z, o);
            part.w += __shfl_xor_sync(0xffffffffu, part.w, o);
        }
        if (lane == 0) redbuf[wid] = part;
    }
    __syncthreads();
    if (tid < ROWS_) {
        const float* rf = (const float*)redbuf;
        float s = c_bout;
        #pragma unroll
        for (int w = 0; w < 8; ++w) s += rf[w * 4 + tid];
        out[b0 + tid] = s;
    }
}

extern "C" void kernel_launch(void* const* d_in, const int* in_sizes, int n_in,
                              void* d_out, int out_size)
{
    (void)in_sizes; (void)n_in; (void)out_size;
    const float* x      = (const float*)d_in[0];
    const float* Win0   = (const float*)d_in[1];
    const float* bin0   = (const float*)d_in[2];
    const float* Wrec0  = (const float*)d_in[3];
    const float* brec0  = (const float*)d_in[4];
    const float* Wattn0 = (const float*)d_in[5];
    const float* battn0 = (const float*)d_in[6];
    const float* Wev0   = (const float*)d_in[7];
    const float* bev0   = (const float*)d_in[8];
    const float* tau0   = (const float*)d_in[9];
    const float* gamma0 = (const float*)d_in[10];
    const float* beta0  = (const float*)d_in[11];
    const float* Win1   = (const float*)d_in[12];
    const float* bin1   = (const float*)d_in[13];
    const float* Wrec1  = (const float*)d_in[14];
    const float* brec1  = (const float*)d_in[15];
    const float* Wattn1 = (const float*)d_in[16];
    const float* battn1 = (const float*)d_in[17];
    const float* Wev1   = (const float*)d_in[18];
    const float* bev1   = (const float*)d_in[19];
    const float* tau1   = (const float*)d_in[20];
    const float* gamma1 = (const float*)d_in[21];
    const float* beta1  = (const float*)d_in[22];
    const float* Wskip  = (const float*)d_in[23];
    const float* bskip  = (const float*)d_in[24];
    const float* Wout   = (const float*)d_in[25];
    const float* bout   = (const float*)d_in[26];

    cudaFuncSetAttribute(liquid_kernel,
                         cudaFuncAttributeMaxDynamicSharedMemorySize, SMEM_BYTES_);

    // Repack the six HxH fp32 matrices into k4-vectorized layout (exact fp32 copy).
    pack_weights<<<(6 * MATP_ + 255) / 256, 256>>>(
        Wattn0, Wrec0, Wattn1, Win1, Wskip, Wrec1);

    liquid_kernel<<<NBLK_, THREADS_, SMEM_BYTES_>>>(x,
        Win0, bin0, brec0, battn0, Wev0, bev0, tau0, gamma0, beta0,
        bin1, brec1, battn1, Wev1, bev1, tau1, gamma1, beta1,
        bskip, Wout, bout, (float*)d_out);
}

// round 12
// speedup vs baseline: 3.0108x; 1.1058x over previous
#include <cuda_runtime.h>
#include <math.h>

#define T_   2048
#define B_   512
#define IN_  32
#define H_   256
#define ROWS_ 4
#define NBLK_ (B_ / ROWS_)
#define THREADS_ 512
#define DT_C  0.1f
#define EPS_C 1e-5f

typedef unsigned long long u64;

// Repacked fp32 weights: 6 matrices [H x H] -> [H/4][H] float4:
// g_Wp[(m*64 + k4)*256 + j] = { W[4k4+0][j], W[4k4+1][j], W[4k4+2][j], W[4k4+3][j] }
// Order m: Wattn0, Wrec0, Wattn1, Win1, Wskip, Wrec1
#define MATP_ (64 * 256)
__device__ float4 g_Wp[6 * MATP_];

// Dynamic SMEM layout (float4 units):
//  [0,256)      h0s       [256,512)   h1s      [512,768)   p1s
//  [768,1024)   gbuf0     [1024,1280) gbuf1    [1280,1536) h0ns
//  [1536,1792)  tbuf
//  [1792,4864)  pb[4][3][256]
//  [4864,4896)  xts       [4896,4928) p0s      [4928,4936) redbuf
//  then floats: params[16][256], wev0s[64], scal[16]
#define SMEM_F4_  4936
#define SMEM_BYTES_ (SMEM_F4_ * 16 + 4096 * 4 + 64 * 4 + 16 * 4)

__device__ __forceinline__ float sigf(float z) { return 1.0f / (1.0f + expf(-z)); }

__device__ __forceinline__ u64 pack_dup(float w) {
    u64 r;
    unsigned int u = __float_as_uint(w);
    asm("mov.b64 %0, {%1, %1};" : "=l"(r) : "r"(u));
    return r;
}
__device__ __forceinline__ void unpack2(u64 v, float& a, float& b) {
    unsigned int lo, hi;
    asm("mov.b64 {%0, %1}, %2;" : "=r"(lo), "=r"(hi) : "l"(v));
    a = __uint_as_float(lo); b = __uint_as_float(hi);
}
__device__ __forceinline__ void fma2(u64& acc, u64 a, u64 b) {
    asm("fma.rn.f32x2 %0, %1, %2, %0;" : "+l"(acc) : "l"(a), "l"(b));
}
#define BAR256() asm volatile("bar.sync 1, 256;" ::: "memory")

__global__ void pack_weights(const float* __restrict__ W0, const float* __restrict__ W1,
                             const float* __restrict__ W2, const float* __restrict__ W3,
                             const float* __restrict__ W4, const float* __restrict__ W5)
{
    int idx = blockIdx.x * blockDim.x + threadIdx.x;
    if (idx >= 6 * MATP_) return;
    const float* Ws[6] = {W0, W1, W2, W3, W4, W5};
    int m  = idx / MATP_;
    int r  = idx - m * MATP_;
    int k4 = r >> 8;
    int j  = r & 255;
    const float* W = Ws[m];
    g_Wp[idx] = make_float4(W[(4 * k4 + 0) * H_ + j], W[(4 * k4 + 1) * H_ + j],
                            W[(4 * k4 + 2) * H_ + j], W[(4 * k4 + 3) * H_ + j]);
}

// Quarter-K (64 k) matvec partial, 2 output columns, shared state loads.
__device__ __forceinline__ void mv2(const float4* __restrict__ wp0,
                                    const float4* __restrict__ wp1,
                                    const float4* st, float4& rA, float4& rB)
{
    u64 a01 = 0ull, a23 = 0ull, b01 = 0ull, b23 = 0ull;
    const ulonglong2* sp = (const ulonglong2*)st;
    #pragma unroll
    for (int k4 = 0; k4 < 16; ++k4) {
        float4 wA = __ldg(&wp0[k4 * H_]);
        float4 wB = __ldg(&wp1[k4 * H_]);
        ulonglong2 s0 = sp[4 * k4 + 0];
        ulonglong2 s1 = sp[4 * k4 + 1];
        ulonglong2 s2 = sp[4 * k4 + 2];
        ulonglong2 s3 = sp[4 * k4 + 3];
        u64 d;
        d = pack_dup(wA.x); fma2(a01, d, s0.x); fma2(a23, d, s0.y);
        d = pack_dup(wB.x); fma2(b01, d, s0.x); fma2(b23, d, s0.y);
        d = pack_dup(wA.y); fma2(a01, d, s1.x); fma2(a23, d, s1.y);
        d = pack_dup(wB.y); fma2(b01, d, s1.x); fma2(b23, d, s1.y);
        d = pack_dup(wA.z); fma2(a01, d, s2.x); fma2(a23, d, s2.y);
        d = pack_dup(wB.z); fma2(b01, d, s2.x); fma2(b23, d, s2.y);
        d = pack_dup(wA.w); fma2(a01, d, s3.x); fma2(a23, d, s3.y);
        d = pack_dup(wB.w); fma2(b01, d, s3.x); fma2(b23, d, s3.y);
    }
    unpack2(a01, rA.x, rA.y); unpack2(a23, rA.z, rA.w);
    unpack2(b01, rB.x, rB.y); unpack2(b23, rB.z, rB.w);
}

// Two matrices over the same state vector, 2 columns each (inp1 + skip).
__device__ __forceinline__ void mv2pair(const float4* __restrict__ wi0,
                                        const float4* __restrict__ wi1,
                                        const float4* __restrict__ ws0,
                                        const float4* __restrict__ ws1,
                                        const float4* st,
                                        float4& riA, float4& riB,
                                        float4& rsA, float4& rsB)
{
    u64 ia01 = 0ull, ia23 = 0ull, ib01 = 0ull, ib23 = 0ull;
    u64 sa01 = 0ull, sa23 = 0ull, sb01 = 0ull, sb23 = 0ull;
    const ulonglong2* sp = (const ulonglong2*)st;
    #pragma unroll
    for (int k4 = 0; k4 < 16; ++k4) {
        float4 wIA = __ldg(&wi0[k4 * H_]);
        float4 wIB = __ldg(&wi1[k4 * H_]);
        float4 wSA = __ldg(&ws0[k4 * H_]);
        float4 wSB = __ldg(&ws1[k4 * H_]);
        ulonglong2 s0 = sp[4 * k4 + 0];
        ulonglong2 s1 = sp[4 * k4 + 1];
        ulonglong2 s2 = sp[4 * k4 + 2];
        ulonglong2 s3 = sp[4 * k4 + 3];
        u64 d;
        d = pack_dup(wIA.x); fma2(ia01, d, s0.x); fma2(ia23, d, s0.y);
        d = pack_dup(wIB.x); fma2(ib01, d, s0.x); fma2(ib23, d, s0.y);
        d = pack_dup(wSA.x); fma2(sa01, d, s0.x); fma2(sa23, d, s0.y);
        d = pack_dup(wSB.x); fma2(sb01, d, s0.x); fma2(sb23, d, s0.y);
        d = pack_dup(wIA.y); fma2(ia01, d, s1.x); fma2(ia23, d, s1.y);
        d = pack_dup(wIB.y); fma2(ib01, d, s1.x); fma2(ib23, d, s1.y);
        d = pack_dup(wSA.y); fma2(sa01, d, s1.x); fma2(sa23, d, s1.y);
        d = pack_dup(wSB.y); fma2(sb01, d, s1.x); fma2(sb23, d, s1.y);
        d = pack_dup(wIA.z); fma2(ia01, d, s2.x); fma2(ia23, d, s2.y);
        d = pack_dup(wIB.z); fma2(ib01, d, s2.x); fma2(ib23, d, s2.y);
        d = pack_dup(wSA.z); fma2(sa01, d, s2.x); fma2(sa23, d, s2.y);
        d = pack_dup(wSB.z); fma2(sb01, d, s2.x); fma2(sb23, d, s2.y);
        d = pack_dup(wIA.w); fma2(ia01, d, s3.x); fma2(ia23, d, s3.y);
        d = pack_dup(wIB.w); fma2(ib01, d, s3.x); fma2(ib23, d, s3.y);
        d = pack_dup(wSA.w); fma2(sa01, d, s3.x); fma2(sa23, d, s3.y);
        d = pack_dup(wSB.w); fma2(sb01, d, s3.x); fma2(sb23, d, s3.y);
    }
    unpack2(ia01, riA.x, riA.y); unpack2(ia23, riA.z, riA.w);
    unpack2(ib01, riB.x, riB.y); unpack2(ib23, riB.z, riB.w);
    unpack2(sa01, rsA.x, rsA.y); unpack2(sa23, rsA.z, rsA.w);
    unpack2(sb01, rsB.x, rsB.y); unpack2(sb23, rsB.z, rsB.w);
}

__global__ void __launch_bounds__(THREADS_, 1)
liquid_kernel(const float* __restrict__ x,
              const float* __restrict__ Win0,  const float* __restrict__ bin0,
              const float* __restrict__ brec0, const float* __restrict__ battn0,
              const float* __restrict__ Wev0,  const float* __restrict__ bev0,
              const float* __restrict__ tau0,  const float* __restrict__ gamma0,
              const float* __restrict__ beta0,
              const float* __restrict__ bin1,  const float* __restrict__ brec1,
              const float* __restrict__ battn1,
              const float* __restrict__ Wev1,  const float* __restrict__ bev1,
              const float* __restrict__ tau1,  const float* __restrict__ gamma1,
              const float* __restrict__ beta1,
              const float* __restrict__ bskip,
              const float* __restrict__ Wout,  const float* __restrict__ bout,
              float* __restrict__ out)
{
    extern __shared__ float4 smem4[];
    float4* h0s   = smem4;
    float4* h1s   = smem4 + 256;
    float4* p1s   = smem4 + 512;
    float4* gbuf0 = smem4 + 768;
    float4* gbuf1 = smem4 + 1024;
    float4* h0ns  = smem4 + 1280;
    float4* tbuf  = smem4 + 1536;
    float4* pb    = smem4 + 1792;            // [4][3][256]
    float4* xts   = smem4 + 4864;            // 32
    float4* p0s   = smem4 + 4896;            // 32
    float4* redbuf = smem4 + 4928;           // 8
    float*  params = (float*)(smem4 + SMEM_F4_);  // 16*256
    float*  wev0s  = params + 4096;               // 64
    float*  scal   = wev0s + 64;                  // ew0[4], ew1[4], mu[4], rs[4]

    const int tid  = threadIdx.x;
    const int lane = tid & 31;
    const int wid  = tid >> 5;
    const int q    = tid >> 7;        // K quarter 0..3
    const int jp   = tid & 127;       // column pair index
    const int j0   = jp, j1 = jp + 128;
    const int b0   = blockIdx.x * ROWS_;

    const float c_bev0 = bev0[0], c_bev1 = bev1[0], c_bout = bout[0];

    // weight bases: matrix m, quarter q, cols j0/j1
    const int qofs = q * 16 * H_;
    const float4* Wa0_0 = g_Wp + 0 * MATP_ + qofs + j0;
    const float4* Wa0_1 = g_Wp + 0 * MATP_ + qofs + j1;
    const float4* Wr0_0 = g_Wp + 1 * MATP_ + qofs + j0;
    const float4* Wr0_1 = g_Wp + 1 * MATP_ + qofs + j1;
    const float4* Wa1_0 = g_Wp + 2 * MATP_ + qofs + j0;
    const float4* Wa1_1 = g_Wp + 2 * MATP_ + qofs + j1;
    const float4* Wi1_0 = g_Wp + 3 * MATP_ + qofs + j0;
    const float4* Wi1_1 = g_Wp + 3 * MATP_ + qofs + j1;
    const float4* Wsk_0 = g_Wp + 4 * MATP_ + qofs + j0;
    const float4* Wsk_1 = g_Wp + 4 * MATP_ + qofs + j1;
    const float4* Wr1_0 = g_Wp + 5 * MATP_ + qofs + j0;
    const float4* Wr1_1 = g_Wp + 5 * MATP_ + qofs + j1;

    const float4 z4 = make_float4(0.f, 0.f, 0.f, 0.f);
    if (tid < 256) {
        int j = tid;
        params[0 * 256 + j]  = battn0[j];
        params[1 * 256 + j]  = brec0[j];
        params[2 * 256 + j]  = bin0[j];
        params[3 * 256 + j]  = battn1[j];
        params[4 * 256 + j]  = brec1[j];
        params[5 * 256 + j]  = bin1[j];
        params[6 * 256 + j]  = bskip[j];
        params[7 * 256 + j]  = gamma0[j];
        params[8 * 256 + j]  = beta0[j];
        params[9 * 256 + j]  = gamma1[j];
        params[10 * 256 + j] = beta1[j];
        params[11 * 256 + j] = DT_C / fminf(fmaxf(tau0[j], 0.1f), 10.0f);
        params[12 * 256 + j] = DT_C / fminf(fmaxf(tau1[j], 0.1f), 10.0f);
        params[13 * 256 + j] = Wev1[j];
        params[14 * 256 + j] = Wev1[H_ + j];
        params[15 * 256 + j] = Wout[j];
        h0s[j] = z4; h1s[j] = z4; p1s[j] = z4;
    }
    if (tid < 2 * IN_) wev0s[tid] = Wev0[tid];
    if (tid < IN_) {
        p0s[tid] = z4;
        // initial x_0 load
        float4 v;
        v.x = x[((size_t)(b0 + 0) * T_) * IN_ + tid];
        v.y = x[((size_t)(b0 + 1) * T_) * IN_ + tid];
        v.z = x[((size_t)(b0 + 2) * T_) * IN_ + tid];
        v.w = x[((size_t)(b0 + 3) * T_) * IN_ + tid];
        xts[tid] = v;
    }
    __syncthreads();

    float* ew0o = out + B_;
    float* ew1o = out + B_ + (size_t)B_ * T_;

    // persistent per-j registers for epilogue threads (tid<256)
    float4 i0 = z4, h0j = z4, h1j = z4, hn = z4;

    for (int t = 0; t < T_; ++t) {
        // ======== P1: attn0 (h0s) + attn1 (h1s) partials; ew0; i0 ========
        if (wid < ROWS_) {
            const float* xf = (const float*)xts;
            const float* pf = (const float*)p0s;
            float s = xf[lane * 4 + wid] * wev0s[lane]
                    + pf[lane * 4 + wid] * wev0s[IN_ + lane];
            #pragma unroll
            for (int o = 16; o > 0; o >>= 1) s += __shfl_xor_sync(0xffffffffu, s, o);
            if (lane == 0) {
                float e = (t > 0) ? sigf(s + c_bev0) : 0.0f;
                scal[wid] = e;
                ew0o[(size_t)(b0 + wid) * T_ + t] = e;
            }
        }
        {
            float4 pA, pB;
            mv2(Wa0_0, Wa0_1, h0s + q * 64, pA, pB);
            pb[(q * 3 + 0) * 256 + j0] = pA;
            pb[(q * 3 + 0) * 256 + j1] = pB;
            mv2(Wa1_0, Wa1_1, h1s + q * 64, pA, pB);
            pb[(q * 3 + 1) * 256 + j0] = pA;
            pb[(q * 3 + 1) * 256 + j1] = pB;
        }
        if (tid < 256) {
            int j = tid;
            float bi = params[2 * 256 + j];
            i0 = make_float4(bi, bi, bi, bi);
            #pragma unroll
            for (int i = 0; i < IN_; ++i) {
                float w = Win0[i * H_ + j];
                float4 xv = xts[i];
                i0.x = fmaf(w, xv.x, i0.x); i0.y = fmaf(w, xv.y, i0.y);
                i0.z = fmaf(w, xv.z, i0.z); i0.w = fmaf(w, xv.w, i0.w);
            }
        }
        __syncthreads();                                    // full #1

        // ======== E1: finalize a0, a1; publish gated states; p0s <- x_t ========
        if (tid < 256) {
            int j = tid;
            float4 s0 = pb[j],       s1 = pb[768 + j];
            float4 s2 = pb[1536 + j], s3 = pb[2304 + j];
            float ba = params[0 * 256 + j];
            float4 a0;
            a0.x = sigf(s0.x + s1.x + s2.x + s3.x + ba);
            a0.y = sigf(s0.y + s1.y + s2.y + s3.y + ba);
            a0.z = sigf(s0.z + s1.z + s2.z + s3.z + ba);
            a0.w = sigf(s0.w + s1.w + s2.w + s3.w + ba);
            h0j = h0s[j];
            gbuf0[j] = make_float4(h0j.x * a0.x, h0j.y * a0.y, h0j.z * a0.z, h0j.w * a0.w);
            s0 = pb[256 + j];  s1 = pb[1024 + j];
            s2 = pb[1792 + j]; s3 = pb[2560 + j];
            float ba1 = params[3 * 256 + j];
            float4 a1;
            a1.x = sigf(s0.x + s1.x + s2.x + s3.x + ba1);
            a1.y = sigf(s0.y + s1.y + s2.y + s3.y + ba1);
            a1.z = sigf(s0.z + s1.z + s2.z + s3.z + ba1);
            a1.w = sigf(s0.w + s1.w + s2.w + s3.w + ba1);
            h1j = h1s[j];
            gbuf1[j] = make_float4(h1j.x * a1.x, h1j.y * a1.y, h1j.z * a1.z, h1j.w * a1.w);
        } else if (tid < 256 + IN_) {
            p0s[tid - 256] = xts[tid - 256];               // save x_t as prev
        }
        __syncthreads();                                    // full #2

        // ======== P2: rec0 (gbuf0) + rec1 (gbuf1) partials ========
        {
            float4 pA, pB;
            mv2(Wr0_0, Wr0_1, gbuf0 + q * 64, pA, pB);
            pb[(q * 3 + 0) * 256 + j0] = pA;
            pb[(q * 3 + 0) * 256 + j1] = pB;
            mv2(Wr1_0, Wr1_1, gbuf1 + q * 64, pA, pB);
            pb[(q * 3 + 2) * 256 + j0] = pA;                // slot2: parked for E5
            pb[(q * 3 + 2) * 256 + j1] = pB;
        }
        __syncthreads();                                    // full #3

        // ======== E2-zone (256-thread barriers): layer-0 update + LN0 + ew1 ========
        if (tid < 256) {
            int j = tid;
            float4 s0 = pb[j],        s1 = pb[768 + j];
            float4 s2 = pb[1536 + j], s3 = pb[2304 + j];
            float br = params[1 * 256 + j];
            float r0x = s0.x + s1.x + s2.x + s3.x + br;
            float r0y = s0.y + s1.y + s2.y + s3.y + br;
            float r0z = s0.z + s1.z + s2.z + s3.z + br;
            float r0w = s0.w + s1.w + s2.w + s3.w + br;
            float rt0 = params[11 * 256 + j];
            const float e0 = 1.f + scal[0], e1 = 1.f + scal[1];
            const float e2 = 1.f + scal[2], e3 = 1.f + scal[3];
            float4 pre;
            pre.x = h0j.x + rt0 * (-h0j.x + tanhf(i0.x) + tanhf(r0x)) * e0;
            pre.y = h0j.y + rt0 * (-h0j.y + tanhf(i0.y) + tanhf(r0y)) * e1;
            pre.z = h0j.z + rt0 * (-h0j.z + tanhf(i0.z) + tanhf(r0z)) * e2;
            pre.w = h0j.w + rt0 * (-h0j.w + tanhf(i0.w) + tanhf(r0w)) * e3;
            tbuf[j] = pre;
            BAR256();
            if (wid < ROWS_) {
                const float* tf = (const float*)tbuf;
                float s = 0.f, ss = 0.f;
                #pragma unroll
                for (int m = 0; m < H_ / 32; ++m) {
                    float v = tf[(lane + 32 * m) * 4 + wid];
                    s += v; ss += v * v;
                }
                #pragma unroll
                for (int o = 16; o > 0; o >>= 1) {
                    s  += __shfl_xor_sync(0xffffffffu, s, o);
                    ss += __shfl_xor_sync(0xffffffffu, ss, o);
                }
                if (lane == 0) {
                    float mu = s * (1.0f / H_);
                    float var = ss * (1.0f / H_) - mu * mu;
                    scal[8 + wid]  = mu;
                    scal[12 + wid] = rsqrtf(var + EPS_C);
                }
            }
            BAR256();
            float g0 = params[7 * 256 + j], be0 = params[8 * 256 + j];
            hn.x = (pre.x - scal[8])  * scal[12] * g0 + be0;
            hn.y = (pre.y - scal[9])  * scal[13] * g0 + be0;
            hn.z = (pre.z - scal[10]) * scal[14] * g0 + be0;
            hn.w = (pre.w - scal[11]) * scal[15] * g0 + be0;
            h0ns[j] = hn;
            h0s[j]  = hn;
            float4 pv = p1s[j];
            float wa = params[13 * 256 + j], wb = params[14 * 256 + j];
            float4 part;
            part.x = hn.x * wa + pv.x * wb;
            part.y = hn.y * wa + pv.y * wb;
            part.z = hn.z * wa + pv.z * wb;
            part.w = hn.w * wa + pv.w * wb;
            #pragma unroll
            for (int o = 16; o > 0; o >>= 1) {
                part.x += __shfl_xor_sync(0xffffffffu, part.x, o);
                part.y += __shfl_xor_sync(0xffffffffu, part.y, o);
                part.z += __shfl_xor_sync(0xffffffffu, part.z, o);
                part.w += __shfl_xor_sync(0xffffffffu, part.w, o);
            }
            if (lane == 0) redbuf[wid] = part;
        }
        __syncthreads();                                    // full #4

        // ======== P3: ew1 final; inp1 + skip (h0ns) partials ========
        if (tid < ROWS_) {
            const float* rf = (const float*)redbuf;
            float s = c_bev1;
            #pragma unroll
            for (int w = 0; w < 8; ++w) s += rf[w * 4 + tid];
            float e = (t > 0) ? sigf(s) : 0.0f;
            scal[4 + tid] = e;
            ew1o[(size_t)(b0 + tid) * T_ + t] = e;
        }
        {
            float4 iA, iB, sA, sB;
            mv2pair(Wi1_0, Wi1_1, Wsk_0, Wsk_1, h0ns + q * 64, iA, iB, sA, sB);
            pb[(q * 3 + 0) * 256 + j0] = iA;
            pb[(q * 3 + 0) * 256 + j1] = iB;
            pb[(q * 3 + 1) * 256 + j0] = sA;
            pb[(q * 3 + 1) * 256 + j1] = sB;
        }
        __syncthreads();                                    // full #5

        // ======== E5-zone: layer-1 update + LN1 + finalize; warps 8-15 prefetch x ========
        if (tid < 256) {
            int j = tid;
            float4 i0q = pb[j],        i1q = pb[768 + j];
            float4 i2q = pb[1536 + j], i3q = pb[2304 + j];
            float4 s0q = pb[256 + j],  s1q = pb[1024 + j];
            float4 s2q = pb[1792 + j], s3q = pb[2560 + j];
            float4 r0q = pb[512 + j],  r1q = pb[1280 + j];
            float4 r2q = pb[2048 + j], r3q = pb[2816 + j];
            float bi = params[5 * 256 + j];
            float bs = params[6 * 256 + j];
            float br = params[4 * 256 + j];
            float i1x = i0q.x + i1q.x + i2q.x + i3q.x + bi;
            float i1y = i0q.y + i1q.y + i2q.y + i3q.y + bi;
            float i1z = i0q.z + i1q.z + i2q.z + i3q.z + bi;
            float i1w = i0q.w + i1q.w + i2q.w + i3q.w + bi;
            float4 skv;
            skv.x = s0q.x + s1q.x + s2q.x + s3q.x + bs;
            skv.y = s0q.y + s1q.y + s2q.y + s3q.y + bs;
            skv.z = s0q.z + s1q.z + s2q.z + s3q.z + bs;
            skv.w = s0q.w + s1q.w + s2q.w + s3q.w + bs;
            float r1x = r0q.x + r1q.x + r2q.x + r3q.x + br;
            float r1y = r0q.y + r1q.y + r2q.y + r3q.y + br;
            float r1z = r0q.z + r1q.z + r2q.z + r3q.z + br;
            float r1w = r0q.w + r1q.w + r2q.w + r3q.w + br;
            float rt1 = params[12 * 256 + j];
            const float e0 = 1.f + scal[4], e1 = 1.f + scal[5];
            const float e2 = 1.f + scal[6], e3 = 1.f + scal[7];
            float4 pre1;
            pre1.x = h1j.x + rt1 * (-h1j.x + tanhf(i1x) + tanhf(r1x)) * e0;
            pre1.y = h1j.y + rt1 * (-h1j.y + tanhf(i1y) + tanhf(r1y)) * e1;
            pre1.z = h1j.z + rt1 * (-h1j.z + tanhf(i1z) + tanhf(r1z)) * e2;
            pre1.w = h1j.w + rt1 * (-h1j.w + tanhf(i1w) + tanhf(r1w)) * e3;
            tbuf[j] = pre1;
            BAR256();
            if (wid < ROWS_) {
                const float* tf = (const float*)tbuf;
                float s = 0.f, ss = 0.f;
                #pragma unroll
                for (int m = 0; m < H_ / 32; ++m) {
                    float v = tf[(lane + 32 * m) * 4 + wid];
                    s += v; ss += v * v;
                }
                #pragma unroll
                for (int o = 16; o > 0; o >>= 1) {
                    s  += __shfl_xor_sync(0xffffffffu, s, o);
                    ss += __shfl_xor_sync(0xffffffffu, ss, o);
                }
                if (lane == 0) {
                    float mu = s * (1.0f / H_);
                    float var = ss * (1.0f / H_) - mu * mu;
                    scal[8 + wid]  = mu;
                    scal[12 + wid] = rsqrtf(var + EPS_C);
                }
            }
            BAR256();
            float g1 = params[9 * 256 + j], be1 = params[10 * 256 + j];
            float4 h1n;
            h1n.x = (pre1.x - scal[8])  * scal[12] * g1 + be1 + skv.x;
            h1n.y = (pre1.y - scal[9])  * scal[13] * g1 + be1 + skv.y;
            h1n.z = (pre1.z - scal[10]) * scal[14] * g1 + be1 + skv.z;
            h1n.w = (pre1.w - scal[11]) * scal[15] * g1 + be1 + skv.w;
            h1s[j] = h1n;
            p1s[j] = hn;
        } else if (tid < 256 + IN_ && t + 1 < T_) {
            // prefetch x_{t+1} while epilogue half runs LN1
            int i = tid - 256;
            float4 v;
            v.x = x[((size_t)(b0 + 0) * T_ + (t + 1)) * IN_ + i];
            v.y = x[((size_t)(b0 + 1) * T_ + (t + 1)) * IN_ + i];
            v.z = x[((size_t)(b0 + 2) * T_ + (t + 1)) * IN_ + i];
            v.w = x[((size_t)(b0 + 3) * T_ + (t + 1)) * IN_ + i];
            xts[i] = v;
        }
        __syncthreads();                                    // full #6
    }

    // ---------- output head ----------
    if (tid < 256) {
        int j = tid;
        float wo = params[15 * 256 + j];
        float4 h = h1s[j];
        float4 part = make_float4(h.x * wo, h.y * wo, h.z * wo, h.w * wo);
        #pragma unroll
        for (int o = 16; o > 0; o >>= 1) {
            part.x += __shfl_xor_sync(0xffffffffu, part.x, o);
            part.y += __shfl_xor_sync(0xffffffffu, part.y, o);
            part.z += __shfl_xor_sync(0xffffffffu, part.z, o);
            part.w += __shfl_xor_sync(0xffffffffu, part.w, o);
        }
        if (lane == 0) redbuf[wid] = part;
    }
    __syncthreads();
    if (tid < ROWS_) {
        const float* rf = (const float*)redbuf;
        float s = c_bout;
        #pragma unroll
        for (int w = 0; w < 8; ++w) s += rf[w * 4 + tid];
        out[b0 + tid] = s;
    }
}

extern "C" void kernel_launch(void* const* d_in, const int* in_sizes, int n_in,
                              void* d_out, int out_size)
{
    (void)in_sizes; (void)n_in; (void)out_size;
    const float* x      = (const float*)d_in[0];
    const float* Win0   = (const float*)d_in[1];
    const float* bin0   = (const float*)d_in[2];
    const float* Wrec0  = (const float*)d_in[3];
    const float* brec0  = (const float*)d_in[4];
    const float* Wattn0 = (const float*)d_in[5];
    const float* battn0 = (const float*)d_in[6];
    const float* Wev0   = (const float*)d_in[7];
    const float* bev0   = (const float*)d_in[8];
    const float* tau0   = (const float*)d_in[9];
    const float* gamma0 = (const float*)d_in[10];
    const float* beta0  = (const float*)d_in[11];
    const float* Win1   = (const float*)d_in[12];
    const float* bin1   = (const float*)d_in[13];
    const float* Wrec1  = (const float*)d_in[14];
    const float* brec1  = (const float*)d_in[15];
    const float* Wattn1 = (const float*)d_in[16];
    const float* battn1 = (const float*)d_in[17];
    const float* Wev1   = (const float*)d_in[18];
    const float* bev1   = (const float*)d_in[19];
    const float* tau1   = (const float*)d_in[20];
    const float* beta1  = (const float*)d_in[22];
    const float* gamma1 = (const float*)d_in[21];
    const float* Wskip  = (const float*)d_in[23];
    const float* bskip  = (const float*)d_in[24];
    const float* Wout   = (const float*)d_in[25];
    const float* bout   = (const float*)d_in[26];

    cudaFuncSetAttribute(liquid_kernel,
                         cudaFuncAttributeMaxDynamicSharedMemorySize, SMEM_BYTES_);

    // Repack the six HxH fp32 matrices into k4-vectorized layout (exact fp32 copy).
    pack_weights<<<(6 * MATP_ + 255) / 256, 256>>>(
        Wattn0, Wrec0, Wattn1, Win1, Wskip, Wrec1);

    liquid_kernel<<<NBLK_, THREADS_, SMEM_BYTES_>>>(x,
        Win0, bin0, brec0, battn0, Wev0, bev0, tau0, gamma0, beta0,
        bin1, brec1, battn1, Wev1, bev1, tau1, gamma1, beta1,
        bskip, Wout, bout, (float*)d_out);
}

// round 13
// speedup vs baseline: 3.0509x; 1.0133x over previous
#include <cuda_runtime.h>
#include <math.h>

#define T_   2048
#define B_   512
#define IN_  32
#define H_   256
#define ROWS_ 4
#define NBLK_ (B_ / ROWS_)
#define THREADS_ 512
#define DT_C  0.1f
#define EPS_C 1e-5f

typedef unsigned long long u64;

// Repacked fp32 weights: 6 matrices [H x H] -> [H/4][H] float4:
// g_Wp[(m*64 + k4)*256 + j] = { W[4k4+0][j], W[4k4+1][j], W[4k4+2][j], W[4k4+3][j] }
// Order m: Wattn0, Wrec0, Wattn1, Win1, Wskip, Wrec1
#define MATP_ (64 * 256)
__device__ float4 g_Wp[6 * MATP_];

// Dynamic SMEM layout (float4 units):
//  [0,256)      h0s       [256,512)   h1s      [512,768)   p1s
//  [768,1024)   gbuf0     [1024,1280) gbuf1    [1280,1536) h0ns
//  [1536,1792)  tbuf
//  [1792,4864)  pb[4][3][256]
//  [4864,4896)  xts       [4896,4928) p0s      [4928,4936) redbuf
//  then floats: params[16][256], wev0s[64], scal[16]
#define SMEM_F4_  4936
#define SMEM_BYTES_ (SMEM_F4_ * 16 + 4096 * 4 + 64 * 4 + 16 * 4)

__device__ __forceinline__ float sigf(float z) { return 1.0f / (1.0f + expf(-z)); }

__device__ __forceinline__ u64 pack_dup(float w) {
    u64 r;
    unsigned int u = __float_as_uint(w);
    asm("mov.b64 %0, {%1, %1};" : "=l"(r) : "r"(u));
    return r;
}
__device__ __forceinline__ void unpack2(u64 v, float& a, float& b) {
    unsigned int lo, hi;
    asm("mov.b64 {%0, %1}, %2;" : "=r"(lo), "=r"(hi) : "l"(v));
    a = __uint_as_float(lo); b = __uint_as_float(hi);
}
__device__ __forceinline__ void fma2(u64& acc, u64 a, u64 b) {
    asm("fma.rn.f32x2 %0, %1, %2, %0;" : "+l"(acc) : "l"(a), "l"(b));
}
#define BAR256() asm volatile("bar.sync 1, 256;" ::: "memory")

__global__ void pack_weights(const float* __restrict__ W0, const float* __restrict__ W1,
                             const float* __restrict__ W2, const float* __restrict__ W3,
                             const float* __restrict__ W4, const float* __restrict__ W5)
{
    int idx = blockIdx.x * blockDim.x + threadIdx.x;
    if (idx >= 6 * MATP_) return;
    const float* Ws[6] = {W0, W1, W2, W3, W4, W5};
    int m  = idx / MATP_;
    int r  = idx - m * MATP_;
    int k4 = r >> 8;
    int j  = r & 255;
    const float* W = Ws[m];
    g_Wp[idx] = make_float4(W[(4 * k4 + 0) * H_ + j], W[(4 * k4 + 1) * H_ + j],
                            W[(4 * k4 + 2) * H_ + j], W[(4 * k4 + 3) * H_ + j]);
}

// Quarter-K (64 k) matvec partial, 2 output columns, shared state loads.
__device__ __forceinline__ void mv2(const float4* __restrict__ wp0,
                                    const float4* __restrict__ wp1,
                                    const float4* st, float4& rA, float4& rB)
{
    u64 a01 = 0ull, a23 = 0ull, b01 = 0ull, b23 = 0ull;
    const ulonglong2* sp = (const ulonglong2*)st;
    #pragma unroll
    for (int k4 = 0; k4 < 16; ++k4) {
        float4 wA = __ldg(&wp0[k4 * H_]);
        float4 wB = __ldg(&wp1[k4 * H_]);
        ulonglong2 s0 = sp[4 * k4 + 0];
        ulonglong2 s1 = sp[4 * k4 + 1];
        ulonglong2 s2 = sp[4 * k4 + 2];
        ulonglong2 s3 = sp[4 * k4 + 3];
        u64 d;
        d = pack_dup(wA.x); fma2(a01, d, s0.x); fma2(a23, d, s0.y);
        d = pack_dup(wB.x); fma2(b01, d, s0.x); fma2(b23, d, s0.y);
        d = pack_dup(wA.y); fma2(a01, d, s1.x); fma2(a23, d, s1.y);
        d = pack_dup(wB.y); fma2(b01, d, s1.x); fma2(b23, d, s1.y);
        d = pack_dup(wA.z); fma2(a01, d, s2.x); fma2(a23, d, s2.y);
        d = pack_dup(wB.z); fma2(b01, d, s2.x); fma2(b23, d, s2.y);
        d = pack_dup(wA.w); fma2(a01, d, s3.x); fma2(a23, d, s3.y);
        d = pack_dup(wB.w); fma2(b01, d, s3.x); fma2(b23, d, s3.y);
    }
    unpack2(a01, rA.x, rA.y); unpack2(a23, rA.z, rA.w);
    unpack2(b01, rB.x, rB.y); unpack2(b23, rB.z, rB.w);
}

// Two matrices over the same state vector, 2 columns each (inp1 + skip).
__device__ __forceinline__ void mv2pair(const float4* __restrict__ wi0,
                                        const float4* __restrict__ wi1,
                                        const float4* __restrict__ ws0,
                                        const float4* __restrict__ ws1,
                                        const float4* st,
                                        float4& riA, float4& riB,
                                        float4& rsA, float4& rsB)
{
    u64 ia01 = 0ull, ia23 = 0ull, ib01 = 0ull, ib23 = 0ull;
    u64 sa01 = 0ull, sa23 = 0ull, sb01 = 0ull, sb23 = 0ull;
    const ulonglong2* sp = (const ulonglong2*)st;
    #pragma unroll
    for (int k4 = 0; k4 < 16; ++k4) {
        float4 wIA = __ldg(&wi0[k4 * H_]);
        float4 wIB = __ldg(&wi1[k4 * H_]);
        float4 wSA = __ldg(&ws0[k4 * H_]);
        float4 wSB = __ldg(&ws1[k4 * H_]);
        ulonglong2 s0 = sp[4 * k4 + 0];
        ulonglong2 s1 = sp[4 * k4 + 1];
        ulonglong2 s2 = sp[4 * k4 + 2];
        ulonglong2 s3 = sp[4 * k4 + 3];
        u64 d;
        d = pack_dup(wIA.x); fma2(ia01, d, s0.x); fma2(ia23, d, s0.y);
        d = pack_dup(wIB.x); fma2(ib01, d, s0.x); fma2(ib23, d, s0.y);
        d = pack_dup(wSA.x); fma2(sa01, d, s0.x); fma2(sa23, d, s0.y);
        d = pack_dup(wSB.x); fma2(sb01, d, s0.x); fma2(sb23, d, s0.y);
        d = pack_dup(wIA.y); fma2(ia01, d, s1.x); fma2(ia23, d, s1.y);
        d = pack_dup(wIB.y); fma2(ib01, d, s1.x); fma2(ib23, d, s1.y);
        d = pack_dup(wSA.y); fma2(sa01, d, s1.x); fma2(sa23, d, s1.y);
        d = pack_dup(wSB.y); fma2(sb01, d, s1.x); fma2(sb23, d, s1.y);
        d = pack_dup(wIA.z); fma2(ia01, d, s2.x); fma2(ia23, d, s2.y);
        d = pack_dup(wIB.z); fma2(ib01, d, s2.x); fma2(ib23, d, s2.y);
        d = pack_dup(wSA.z); fma2(sa01, d, s2.x); fma2(sa23, d, s2.y);
        d = pack_dup(wSB.z); fma2(sb01, d, s2.x); fma2(sb23, d, s2.y);
        d = pack_dup(wIA.w); fma2(ia01, d, s3.x); fma2(ia23, d, s3.y);
        d = pack_dup(wIB.w); fma2(ib01, d, s3.x); fma2(ib23, d, s3.y);
        d = pack_dup(wSA.w); fma2(sa01, d, s3.x); fma2(sa23, d, s3.y);
        d = pack_dup(wSB.w); fma2(sb01, d, s3.x); fma2(sb23, d, s3.y);
    }
    unpack2(ia01, riA.x, riA.y); unpack2(ia23, riA.z, riA.w);
    unpack2(ib01, riB.x, riB.y); unpack2(ib23, riB.z, riB.w);
    unpack2(sa01, rsA.x, rsA.y); unpack2(sa23, rsA.z, rsA.w);
    unpack2(sb01, rsB.x, rsB.y); unpack2(sb23, rsB.z, rsB.w);
}

__global__ void __launch_bounds__(THREADS_, 1)
liquid_kernel(const float* __restrict__ x,
              const float* __restrict__ Win0,  const float* __restrict__ bin0,
              const float* __restrict__ brec0, const float* __restrict__ battn0,
              const float* __restrict__ Wev0,  const float* __restrict__ bev0,
              const float* __restrict__ tau0,  const float* __restrict__ gamma0,
              const float* __restrict__ beta0,
              const float* __restrict__ bin1,  const float* __restrict__ brec1,
              const float* __restrict__ battn1,
              const float* __restrict__ Wev1,  const float* __restrict__ bev1,
              const float* __restrict__ tau1,  const float* __restrict__ gamma1,
              const float* __restrict__ beta1,
              const float* __restrict__ bskip,
              const float* __restrict__ Wout,  const float* __restrict__ bout,
              float* __restrict__ out)
{
    extern __shared__ float4 smem4[];
    float4* h0s   = smem4;
    float4* h1s   = smem4 + 256;
    float4* p1s   = smem4 + 512;
    float4* gbuf0 = smem4 + 768;
    float4* gbuf1 = smem4 + 1024;
    float4* h0ns  = smem4 + 1280;
    float4* tbuf  = smem4 + 1536;
    float4* pb    = smem4 + 1792;            // [4][3][256]
    float4* xts   = smem4 + 4864;            // 32
    float4* p0s   = smem4 + 4896;            // 32
    float4* redbuf = smem4 + 4928;           // 8
    float*  params = (float*)(smem4 + SMEM_F4_);  // 16*256
    float*  wev0s  = params + 4096;               // 64
    float*  scal   = wev0s + 64;                  // ew0[4], ew1[4], mu[4], rs[4]

    const int tid  = threadIdx.x;
    const int lane = tid & 31;
    const int wid  = tid >> 5;
    const int q    = tid >> 7;        // K quarter 0..3
    const int jp   = tid & 127;       // column pair index
    const int j0   = jp, j1 = jp + 128;
    const int b0   = blockIdx.x * ROWS_;

    const float c_bev0 = bev0[0], c_bev1 = bev1[0], c_bout = bout[0];

    // weight bases: matrix m, quarter q, cols j0/j1
    const int qofs = q * 16 * H_;
    const float4* Wa0_0 = g_Wp + 0 * MATP_ + qofs + j0;
    const float4* Wa0_1 = g_Wp + 0 * MATP_ + qofs + j1;
    const float4* Wr0_0 = g_Wp + 1 * MATP_ + qofs + j0;
    const float4* Wr0_1 = g_Wp + 1 * MATP_ + qofs + j1;
    const float4* Wa1_0 = g_Wp + 2 * MATP_ + qofs + j0;
    const float4* Wa1_1 = g_Wp + 2 * MATP_ + qofs + j1;
    const float4* Wi1_0 = g_Wp + 3 * MATP_ + qofs + j0;
    const float4* Wi1_1 = g_Wp + 3 * MATP_ + qofs + j1;
    const float4* Wsk_0 = g_Wp + 4 * MATP_ + qofs + j0;
    const float4* Wsk_1 = g_Wp + 4 * MATP_ + qofs + j1;

    const float4 z4 = make_float4(0.f, 0.f, 0.f, 0.f);
    if (tid < 256) {
        int j = tid;
        params[0 * 256 + j]  = battn0[j];
        params[1 * 256 + j]  = brec0[j];
        params[2 * 256 + j]  = bin0[j];
        params[3 * 256 + j]  = battn1[j];
        params[4 * 256 + j]  = brec1[j];
        params[5 * 256 + j]  = bin1[j];
        params[6 * 256 + j]  = bskip[j];
        params[7 * 256 + j]  = gamma0[j];
        params[8 * 256 + j]  = beta0[j];
        params[9 * 256 + j]  = gamma1[j];
        params[10 * 256 + j] = beta1[j];
        params[11 * 256 + j] = DT_C / fminf(fmaxf(tau0[j], 0.1f), 10.0f);
        params[12 * 256 + j] = DT_C / fminf(fmaxf(tau1[j], 0.1f), 10.0f);
        params[13 * 256 + j] = Wev1[j];
        params[14 * 256 + j] = Wev1[H_ + j];
        params[15 * 256 + j] = Wout[j];
        h0s[j] = z4; h1s[j] = z4; p1s[j] = z4;
    }
    if (tid < 2 * IN_) wev0s[tid] = Wev0[tid];
    if (tid < IN_) {
        p0s[tid] = z4;
        // initial x_0 load
        float4 v;
        v.x = x[((size_t)(b0 + 0) * T_) * IN_ + tid];
        v.y = x[((size_t)(b0 + 1) * T_) * IN_ + tid];
        v.z = x[((size_t)(b0 + 2) * T_) * IN_ + tid];
        v.w = x[((size_t)(b0 + 3) * T_) * IN_ + tid];
        xts[tid] = v;
    }
    __syncthreads();

    float* ew0o = out + B_;
    float* ew1o = out + B_ + (size_t)B_ * T_;

    // persistent per-j registers for epilogue threads (tid<256)
    float4 i0 = z4, h0j = z4, hn = z4;

    for (int t = 0; t < T_; ++t) {
        // ======== P1: attn0 (h0s) + attn1 (h1s) partials; ew0; i0 ========
        if (wid < ROWS_) {
            const float* xf = (const float*)xts;
            const float* pf = (const float*)p0s;
            float s = xf[lane * 4 + wid] * wev0s[lane]
                    + pf[lane * 4 + wid] * wev0s[IN_ + lane];
            #pragma unroll
            for (int o = 16; o > 0; o >>= 1) s += __shfl_xor_sync(0xffffffffu, s, o);
            if (lane == 0) {
                float e = (t > 0) ? sigf(s + c_bev0) : 0.0f;
                scal[wid] = e;
                ew0o[(size_t)(b0 + wid) * T_ + t] = e;
            }
        }
        {
            float4 pA, pB;
            mv2(Wa0_0, Wa0_1, h0s + q * 64, pA, pB);
            pb[(q * 3 + 0) * 256 + j0] = pA;
            pb[(q * 3 + 0) * 256 + j1] = pB;
            mv2(Wa1_0, Wa1_1, h1s + q * 64, pA, pB);
            pb[(q * 3 + 1) * 256 + j0] = pA;
            pb[(q * 3 + 1) * 256 + j1] = pB;
        }
        if (tid < 256) {
            int j = tid;
            float bi = params[2 * 256 + j];
            i0 = make_float4(bi, bi, bi, bi);
            #pragma unroll
            for (int i = 0; i < IN_; ++i) {
                float w = Win0[i * H_ + j];
                float4 xv = xts[i];
                i0.x = fmaf(w, xv.x, i0.x); i0.y = fmaf(w, xv.y, i0.y);
                i0.z = fmaf(w, xv.z, i0.z); i0.w = fmaf(w, xv.w, i0.w);
            }
        }
        __syncthreads();                                    // full #1

        // ======== E1 (split over 512): finalize a0 (lower), a1 (upper) ========
        if (tid < 256) {
            int j = tid;
            float4 s0 = pb[j],        s1 = pb[768 + j];
            float4 s2 = pb[1536 + j], s3 = pb[2304 + j];
            float ba = params[0 * 256 + j];
            float4 a0;
            a0.x = sigf(s0.x + s1.x + s2.x + s3.x + ba);
            a0.y = sigf(s0.y + s1.y + s2.y + s3.y + ba);
            a0.z = sigf(s0.z + s1.z + s2.z + s3.z + ba);
            a0.w = sigf(s0.w + s1.w + s2.w + s3.w + ba);
            h0j = h0s[j];
            gbuf0[j] = make_float4(h0j.x * a0.x, h0j.y * a0.y, h0j.z * a0.z, h0j.w * a0.w);
            if (j < IN_) p0s[j] = xts[j];                  // save x_t as prev
        } else {
            int j = tid - 256;
            float4 s0 = pb[256 + j],  s1 = pb[1024 + j];
            float4 s2 = pb[1792 + j], s3 = pb[2560 + j];
            float ba1 = params[3 * 256 + j];
            float4 a1;
            a1.x = sigf(s0.x + s1.x + s2.x + s3.x + ba1);
            a1.y = sigf(s0.y + s1.y + s2.y + s3.y + ba1);
            a1.z = sigf(s0.z + s1.z + s2.z + s3.z + ba1);
            a1.w = sigf(s0.w + s1.w + s2.w + s3.w + ba1);
            float4 h1v = h1s[j];
            gbuf1[j] = make_float4(h1v.x * a1.x, h1v.y * a1.y, h1v.z * a1.z, h1v.w * a1.w);
        }
        __syncthreads();                                    // full #2

        // ======== P2: rec0 (gbuf0) partials only ========
        {
            float4 pA, pB;
            mv2(Wr0_0, Wr0_1, gbuf0 + q * 64, pA, pB);
            pb[(q * 3 + 0) * 256 + j0] = pA;
            pb[(q * 3 + 0) * 256 + j1] = pB;
        }
        __syncthreads();                                    // full #3

        // ======== Split zone: layer-0 epilogue (lower) || rec1 (upper) ========
        if (tid < 256) {
            int j = tid;
            float4 s0 = pb[j],        s1 = pb[768 + j];
            float4 s2 = pb[1536 + j], s3 = pb[2304 + j];
            float br = params[1 * 256 + j];
            float r0x = s0.x + s1.x + s2.x + s3.x + br;
            float r0y = s0.y + s1.y + s2.y + s3.y + br;
            float r0z = s0.z + s1.z + s2.z + s3.z + br;
            float r0w = s0.w + s1.w + s2.w + s3.w + br;
            float rt0 = params[11 * 256 + j];
            const float e0 = 1.f + scal[0], e1 = 1.f + scal[1];
            const float e2 = 1.f + scal[2], e3 = 1.f + scal[3];
            float4 pre;
            pre.x = h0j.x + rt0 * (-h0j.x + tanhf(i0.x) + tanhf(r0x)) * e0;
            pre.y = h0j.y + rt0 * (-h0j.y + tanhf(i0.y) + tanhf(r0y)) * e1;
            pre.z = h0j.z + rt0 * (-h0j.z + tanhf(i0.z) + tanhf(r0z)) * e2;
            pre.w = h0j.w + rt0 * (-h0j.w + tanhf(i0.w) + tanhf(r0w)) * e3;
            tbuf[j] = pre;
            BAR256();
            if (wid < ROWS_) {
                const float* tf = (const float*)tbuf;
                float s = 0.f, ss = 0.f;
                #pragma unroll
                for (int m = 0; m < H_ / 32; ++m) {
                    float v = tf[(lane + 32 * m) * 4 + wid];
                    s += v; ss += v * v;
                }
                #pragma unroll
                for (int o = 16; o > 0; o >>= 1) {
                    s  += __shfl_xor_sync(0xffffffffu, s, o);
                    ss += __shfl_xor_sync(0xffffffffu, ss, o);
                }
                if (lane == 0) {
                    float mu = s * (1.0f / H_);
                    float var = ss * (1.0f / H_) - mu * mu;
                    scal[8 + wid]  = mu;
                    scal[12 + wid] = rsqrtf(var + EPS_C);
                }
            }
            BAR256();
            float g0 = params[7 * 256 + j], be0 = params[8 * 256 + j];
            hn.x = (pre.x - scal[8])  * scal[12] * g0 + be0;
            hn.y = (pre.y - scal[9])  * scal[13] * g0 + be0;
            hn.z = (pre.z - scal[10]) * scal[14] * g0 + be0;
            hn.w = (pre.w - scal[11]) * scal[15] * g0 + be0;
            h0ns[j] = hn;
            h0s[j]  = hn;
            float4 pv = p1s[j];
            float wa = params[13 * 256 + j], wb = params[14 * 256 + j];
            float4 part;
            part.x = hn.x * wa + pv.x * wb;
            part.y = hn.y * wa + pv.y * wb;
            part.z = hn.z * wa + pv.z * wb;
            part.w = hn.w * wa + pv.w * wb;
            #pragma unroll
            for (int o = 16; o > 0; o >>= 1) {
                part.x += __shfl_xor_sync(0xffffffffu, part.x, o);
                part.y += __shfl_xor_sync(0xffffffffu, part.y, o);
                part.z += __shfl_xor_sync(0xffffffffu, part.z, o);
                part.w += __shfl_xor_sync(0xffffffffu, part.w, o);
            }
            if (lane == 0) redbuf[wid] = part;
        } else {
            // rec1: quarters (qlo, qlo+1), cols (jq, jq+128) — same work items
            // and FMA grouping as R12 (bit-exact), parked in pb slots idx 2,5,8,11.
            int t2 = tid - 256;
            int jq = t2 & 127;
            int qlo = (t2 >> 7) << 1;                       // 0 or 2
            const float4* base = g_Wp + 5 * MATP_ + jq;
            const float4* Wq0_0 = base + (qlo * 16) * H_;
            const float4* Wq0_1 = Wq0_0 + 128;
            const float4* Wq1_0 = base + ((qlo + 1) * 16) * H_;
            const float4* Wq1_1 = Wq1_0 + 128;
            float4 pA, pB;
            mv2(Wq0_0, Wq0_1, gbuf1 + qlo * 64, pA, pB);
            pb[(qlo * 3 + 2) * 256 + jq]       = pA;
            pb[(qlo * 3 + 2) * 256 + jq + 128] = pB;
            mv2(Wq1_0, Wq1_1, gbuf1 + (qlo + 1) * 64, pA, pB);
            pb[((qlo + 1) * 3 + 2) * 256 + jq]       = pA;
            pb[((qlo + 1) * 3 + 2) * 256 + jq + 128] = pB;
        }
        __syncthreads();                                    // full #4

        // ======== P3: ew1 final; inp1 + skip (h0ns) partials ========
        if (tid < ROWS_) {
            const float* rf = (const float*)redbuf;
            float s = c_bev1;
            #pragma unroll
            for (int w = 0; w < 8; ++w) s += rf[w * 4 + tid];
            float e = (t > 0) ? sigf(s) : 0.0f;
            scal[4 + tid] = e;
            ew1o[(size_t)(b0 + tid) * T_ + t] = e;
        }
        {
            float4 iA, iB, sA, sB;
            mv2pair(Wi1_0, Wi1_1, Wsk_0, Wsk_1, h0ns + q * 64, iA, iB, sA, sB);
            pb[(q * 3 + 0) * 256 + j0] = iA;
            pb[(q * 3 + 0) * 256 + j1] = iB;
            pb[(q * 3 + 1) * 256 + j0] = sA;
            pb[(q * 3 + 1) * 256 + j1] = sB;
        }
        __syncthreads();                                    // full #5

        // ======== E5-zone: layer-1 update + LN1 + finalize; warp 8 prefetches x ========
        if (tid < 256) {
            int j = tid;
            float4 i0q = pb[j],        i1q = pb[768 + j];
            float4 i2q = pb[1536 + j], i3q = pb[2304 + j];
            float4 s0q = pb[256 + j],  s1q = pb[1024 + j];
            float4 s2q = pb[1792 + j], s3q = pb[2560 + j];
            float4 r0q = pb[512 + j],  r1q = pb[1280 + j];
            float4 r2q = pb[2048 + j], r3q = pb[2816 + j];
            float4 h1j = h1s[j];
            float bi = params[5 * 256 + j];
            float bs = params[6 * 256 + j];
            float br = params[4 * 256 + j];
            float i1x = i0q.x + i1q.x + i2q.x + i3q.x + bi;
            float i1y = i0q.y + i1q.y + i2q.y + i3q.y + bi;
            float i1z = i0q.z + i1q.z + i2q.z + i3q.z + bi;
            float i1w = i0q.w + i1q.w + i2q.w + i3q.w + bi;
            float4 skv;
            skv.x = s0q.x + s1q.x + s2q.x + s3q.x + bs;
            skv.y = s0q.y + s1q.y + s2q.y + s3q.y + bs;
            skv.z = s0q.z + s1q.z + s2q.z + s3q.z + bs;
            skv.w = s0q.w + s1q.w + s2q.w + s3q.w + bs;
            float r1x = r0q.x + r1q.x + r2q.x + r3q.x + br;
            float r1y = r0q.y + r1q.y + r2q.y + r3q.y + br;
            float r1z = r0q.z + r1q.z + r2q.z + r3q.z + br;
            float r1w = r0q.w + r1q.w + r2q.w + r3q.w + br;
            float rt1 = params[12 * 256 + j];
            const float e0 = 1.f + scal[4], e1 = 1.f + scal[5];
            const float e2 = 1.f + scal[6], e3 = 1.f + scal[7];
            float4 pre1;
            pre1.x = h1j.x + rt1 * (-h1j.x + tanhf(i1x) + tanhf(r1x)) * e0;
            pre1.y = h1j.y + rt1 * (-h1j.y + tanhf(i1y) + tanhf(r1y)) * e1;
            pre1.z = h1j.z + rt1 * (-h1j.z + tanhf(i1z) + tanhf(r1z)) * e2;
            pre1.w = h1j.w + rt1 * (-h1j.w + tanhf(i1w) + tanhf(r1w)) * e3;
            tbuf[j] = pre1;
            BAR256();
            if (wid < ROWS_) {
                const float* tf = (const float*)tbuf;
                float s = 0.f, ss = 0.f;
                #pragma unroll
                for (int m = 0; m < H_ / 32; ++m) {
                    float v = tf[(lane + 32 * m) * 4 + wid];
                    s += v; ss += v * v;
                }
                #pragma unroll
                for (int o = 16; o > 0; o >>= 1) {
                    s  += __shfl_xor_sync(0xffffffffu, s, o);
                    ss += __shfl_xor_sync(0xffffffffu, ss, o);
                }
                if (lane == 0) {
                    float mu = s * (1.0f / H_);
                    float var = ss * (1.0f / H_) - mu * mu;
                    scal[8 + wid]  = mu;
                    scal[12 + wid] = rsqrtf(var + EPS_C);
                }
            }
            BAR256();
            float g1 = params[9 * 256 + j], be1 = params[10 * 256 + j];
            float4 h1n;
            h1n.x = (pre1.x - scal[8])  * scal[12] * g1 + be1 + skv.x;
            h1n.y = (pre1.y - scal[9])  * scal[13] * g1 + be1 + skv.y;
            h1n.z = (pre1.z - scal[10]) * scal[14] * g1 + be1 + skv.z;
            h1n.w = (pre1.w - scal[11]) * scal[15] * g1 + be1 + skv.w;
            h1s[j] = h1n;
            p1s[j] = hn;
        } else if (tid < 256 + IN_ && t + 1 < T_) {
            // prefetch x_{t+1} while epilogue half runs LN1
            int i = tid - 256;
            float4 v;
            v.x = x[((size_t)(b0 + 0) * T_ + (t + 1)) * IN_ + i];
            v.y = x[((size_t)(b0 + 1) * T_ + (t + 1)) * IN_ + i];
            v.z = x[((size_t)(b0 + 2) * T_ + (t + 1)) * IN_ + i];
            v.w = x[((size_t)(b0 + 3) * T_ + (t + 1)) * IN_ + i];
            xts[i] = v;
        }
        __syncthreads();                                    // full #6
    }

    // ---------- output head ----------
    if (tid < 256) {
        int j = tid;
        float wo = params[15 * 256 + j];
        float4 h = h1s[j];
        float4 part = make_float4(h.x * wo, h.y * wo, h.z * wo, h.w * wo);
        #pragma unroll
        for (int o = 16; o > 0; o >>= 1) {
            part.x += __shfl_xor_sync(0xffffffffu, part.x, o);
            part.y += __shfl_xor_sync(0xffffffffu, part.y, o);
            part.z += __shfl_xor_sync(0xffffffffu, part.z, o);
            part.w += __shfl_xor_sync(0xffffffffu, part.w, o);
        }
        if (lane == 0) redbuf[wid] = part;
    }
    __syncthreads();
    if (tid < ROWS_) {
        const float* rf = (const float*)redbuf;
        float s = c_bout;
        #pragma unroll
        for (int w = 0; w < 8; ++w) s += rf[w * 4 + tid];
        out[b0 + tid] = s;
    }
}

extern "C" void kernel_launch(void* const* d_in, const int* in_sizes, int n_in,
                              void* d_out, int out_size)
{
    (void)in_sizes; (void)n_in; (void)out_size;
    const float* x      = (const float*)d_in[0];
    const float* Win0   = (const float*)d_in[1];
    const float* bin0   = (const float*)d_in[2];
    const float* Wrec0  = (const float*)d_in[3];
    const float* brec0  = (const float*)d_in[4];
    const float* Wattn0 = (const float*)d_in[5];
    const float* battn0 = (const float*)d_in[6];
    const float* Wev0   = (const float*)d_in[7];
    const float* bev0   = (const float*)d_in[8];
    const float* tau0   = (const float*)d_in[9];
    const float* gamma0 = (const float*)d_in[10];
    const float* beta0  = (const float*)d_in[11];
    const float* Win1   = (const float*)d_in[12];
    const float* bin1   = (const float*)d_in[13];
    const float* Wrec1  = (const float*)d_in[14];
    const float* brec1  = (const float*)d_in[15];
    const float* Wattn1 = (const float*)d_in[16];
    const float* battn1 = (const float*)d_in[17];
    const float* Wev1   = (const float*)d_in[18];
    const float* bev1   = (const float*)d_in[19];
    const float* tau1   = (const float*)d_in[20];
    const float* gamma1 = (const float*)d_in[21];
    const float* beta1  = (const float*)d_in[22];
    const float* Wskip  = (const float*)d_in[23];
    const float* bskip  = (const float*)d_in[24];
    const float* Wout   = (const float*)d_in[25];
    const float* bout   = (const float*)d_in[26];

    cudaFuncSetAttribute(liquid_kernel,
                         cudaFuncAttributeMaxDynamicSharedMemorySize, SMEM_BYTES_);

    // Repack the six HxH fp32 matrices into k4-vectorized layout (exact fp32 copy).
    pack_weights<<<(6 * MATP_ + 255) / 256, 256>>>(
        Wattn0, Wrec0, Wattn1, Win1, Wskip, Wrec1);

    liquid_kernel<<<NBLK_, THREADS_, SMEM_BYTES_>>>(x,
        Win0, bin0, brec0, battn0, Wev0, bev0, tau0, gamma0, beta0,
        bin1, brec1, battn1, Wev1, bev1, tau1, gamma1, beta1,
        bskip, Wout, bout, (float*)d_out);
}